// round 12
// baseline (speedup 1.0000x reference)
#include <cuda_runtime.h>
#include <cuda_bf16.h>
#include <cstdint>

#define BATCH 2
#define SEQ   2048
#define HEADS 16
#define HD    64
#define EMB   1024
#define MROWS (BATCH*SEQ)
#define QKVN  (3*EMB)
#define NKT   (SEQ/64)           // 32 key tiles

// roped q, fp32 dense [MROWS][EMB]
__device__ float g_q[(size_t)MROWS * EMB];                               // 16.8 MB
// K/V tiles, {hi,lo}-interleaved bf16x2 words (see round-11 layout comment)
__device__ uint32_t g_kvsp[(size_t)BATCH * HEADS * NKT * 8192];          // 67.1 MB
// Pre-split GEMM operands: [kp][M or N] word = {v[2kp][*], v[2kp+1][*]}
__device__ uint32_t g_xh[(size_t)(EMB/2) * MROWS],  g_xl[(size_t)(EMB/2) * MROWS];
__device__ uint32_t g_wqh[(size_t)(EMB/2) * QKVN],  g_wql[(size_t)(EMB/2) * QKVN];
__device__ uint32_t g_wph[(size_t)(EMB/2) * EMB],   g_wpl[(size_t)(EMB/2) * EMB];
__device__ uint32_t g_ah[(size_t)(EMB/2) * MROWS],  g_al[(size_t)(EMB/2) * MROWS];

__device__ __forceinline__ uint32_t pack_bf16x2(float e0, float e1) {
    uint32_t r;
    asm("cvt.rn.bf16x2.f32 %0, %1, %2;" : "=r"(r) : "f"(e1), "f"(e0));
    return r;
}
__device__ __forceinline__ void split2(float x, float y, uint32_t& hp, uint32_t& lp) {
    float hx = __bfloat162float(__float2bfloat16_rn(x));
    float hy = __bfloat162float(__float2bfloat16_rn(y));
    hp = pack_bf16x2(hx, hy);
    lp = pack_bf16x2(x - hx, y - hy);
}
__device__ __forceinline__ void mma_bf16(float c[4], const uint32_t a[4], const uint32_t b[2]) {
    asm volatile(
        "mma.sync.aligned.m16n8k16.row.col.f32.bf16.bf16.f32 "
        "{%0,%1,%2,%3}, {%4,%5,%6,%7}, {%8,%9}, {%0,%1,%2,%3};"
        : "+f"(c[0]), "+f"(c[1]), "+f"(c[2]), "+f"(c[3])
        : "r"(a[0]), "r"(a[1]), "r"(a[2]), "r"(a[3]), "r"(b[0]), "r"(b[1]));
}
__device__ __forceinline__ void cp16(uint32_t dst, const void* src) {
    asm volatile("cp.async.cg.shared.global [%0], [%1], 16;" :: "r"(dst), "l"(src));
}
__device__ __forceinline__ void cp_commit() {
    asm volatile("cp.async.commit_group;");
}

// ---------------------------------------------------------------------------
// prep_a (unchanged)
// ---------------------------------------------------------------------------
__global__ __launch_bounds__(256) void prep_a(const float* __restrict__ A,
                                              uint32_t* __restrict__ dh,
                                              uint32_t* __restrict__ dl)
{
    __shared__ float stage[64 * 33];
    const int tid = threadIdx.x;
    const int k0 = blockIdx.x * 32;
    const int m0 = blockIdx.y * 64;

    #pragma unroll
    for (int j = 0; j < 2; j++) {
        const int f = tid + j * 256;
        const int r = f >> 3;
        const int c4 = (f & 7) * 4;
        float4 v = *(const float4*)&A[(size_t)(m0 + r) * EMB + k0 + c4];
        stage[r * 33 + c4 + 0] = v.x;
        stage[r * 33 + c4 + 1] = v.y;
        stage[r * 33 + c4 + 2] = v.z;
        stage[r * 33 + c4 + 3] = v.w;
    }
    __syncthreads();

    const int m_l = tid & 63;
    #pragma unroll
    for (int j = 0; j < 4; j++) {
        const int kp_l = (tid >> 6) + j * 4;
        float a = stage[m_l * 33 + 2 * kp_l];
        float b = stage[m_l * 33 + 2 * kp_l + 1];
        uint32_t h, l;
        split2(a, b, h, l);
        dh[(size_t)(k0 / 2 + kp_l) * MROWS + m0 + m_l] = h;
        dl[(size_t)(k0 / 2 + kp_l) * MROWS + m0 + m_l] = l;
    }
}

// ---------------------------------------------------------------------------
// prep_w (unchanged)
// ---------------------------------------------------------------------------
__global__ __launch_bounds__(128) void prep_w(const float* __restrict__ W,
                                              uint32_t* __restrict__ dh,
                                              uint32_t* __restrict__ dl, int N)
{
    const int n  = blockIdx.x * 512 + threadIdx.x * 4;
    const int kp = blockIdx.y;
    float4 r0 = *(const float4*)&W[(size_t)(2 * kp) * N + n];
    float4 r1 = *(const float4*)&W[(size_t)(2 * kp + 1) * N + n];
    uint32_t h[4], l[4];
    split2(r0.x, r1.x, h[0], l[0]);
    split2(r0.y, r1.y, h[1], l[1]);
    split2(r0.z, r1.z, h[2], l[2]);
    split2(r0.w, r1.w, h[3], l[3]);
    *(uint4*)&dh[(size_t)kp * N + n] = make_uint4(h[0], h[1], h[2], h[3]);
    *(uint4*)&dl[(size_t)kp * N + n] = make_uint4(l[0], l[1], l[2], l[3]);
}

// ---------------------------------------------------------------------------
// 3xBF16 GEMM on pre-split operands (unchanged from round 11; 216us QKV)
// ---------------------------------------------------------------------------
__global__ __launch_bounds__(256, 2) void gemm_sp(
    const uint32_t* __restrict__ AhG, const uint32_t* __restrict__ AlG,
    const uint32_t* __restrict__ BhG, const uint32_t* __restrict__ BlG,
    float* __restrict__ C, int Ndim,
    const float* __restrict__ freqs,
    const float* __restrict__ bvec, int mode)
{
    extern __shared__ uint32_t sm[];
    uint32_t smb;
    {
        uint64_t t;
        asm("cvta.to.shared.u64 %0, %1;" : "=l"(t) : "l"(sm));
        smb = (uint32_t)t;
    }

    const int tid  = threadIdx.x;
    const int lane = tid & 31;
    const int warp = tid >> 5;
    const int g    = lane >> 2;
    const int tg   = lane & 3;
    const int warp_m = warp >> 2;
    const int warp_n = warp & 3;
    const int m0 = blockIdx.y * 128;
    const int n0 = blockIdx.x * 128;

    float acc[4][4][4];
    #pragma unroll
    for (int mt = 0; mt < 4; mt++)
        #pragma unroll
        for (int nt = 0; nt < 4; nt++)
            #pragma unroll
            for (int c = 0; c < 4; c++) acc[mt][nt][c] = 0.0f;

    const uint32_t* gArr[4] = {AhG, AlG, BhG, BlG};

    {
        #pragma unroll
        for (int i = 0; i < 8; i++) {
            const int f = tid + i * 256;
            const int arr = f >> 9, r = (f >> 5) & 15, seg = f & 31;
            const uint32_t* src = (arr < 2)
                ? gArr[arr] + (size_t)r * MROWS + m0 + seg * 4
                : gArr[arr] + (size_t)r * Ndim + n0 + seg * 4;
            cp16(smb + (uint32_t)(arr * 2176 + r * 136 + seg * 4) * 4u, src);
        }
        cp_commit();
    }

    const int NIT = EMB / 32;
    for (int it = 0; it < NIT; it++) {
        const int cur = it & 1;
        if (it + 1 < NIT) {
            const int kp0 = (it + 1) * 16;
            const uint32_t sb = smb + (uint32_t)((cur ^ 1) * 8704) * 4u;
            #pragma unroll
            for (int i = 0; i < 8; i++) {
                const int f = tid + i * 256;
                const int arr = f >> 9, r = (f >> 5) & 15, seg = f & 31;
                const uint32_t* src = (arr < 2)
                    ? gArr[arr] + (size_t)(kp0 + r) * MROWS + m0 + seg * 4
                    : gArr[arr] + (size_t)(kp0 + r) * Ndim + n0 + seg * 4;
                cp16(sb + (uint32_t)(arr * 2176 + r * 136 + seg * 4) * 4u, src);
            }
            cp_commit();
            asm volatile("cp.async.wait_group 1;");
        } else {
            asm volatile("cp.async.wait_group 0;");
        }
        __syncthreads();

        const uint32_t* Ah = sm + cur * 8704;
        const uint32_t* Al = Ah + 2176;
        const uint32_t* Bh = Ah + 4352;
        const uint32_t* Bl = Ah + 6528;

        #pragma unroll
        for (int kc = 0; kc < 2; kc++) {
            uint32_t bh[4][2], bl[4][2];
            #pragma unroll
            for (int nt = 0; nt < 4; nt++) {
                const int nc = warp_n * 32 + nt * 8 + g;
                bh[nt][0] = Bh[(kc * 8 + tg) * 136 + nc];
                bh[nt][1] = Bh[(kc * 8 + tg + 4) * 136 + nc];
                bl[nt][0] = Bl[(kc * 8 + tg) * 136 + nc];
                bl[nt][1] = Bl[(kc * 8 + tg + 4) * 136 + nc];
            }
            #pragma unroll
            for (int mt = 0; mt < 4; mt++) {
                const int mr = warp_m * 64 + mt * 16;
                uint32_t ah[4], al_[4];
                ah[0]  = Ah[(kc * 8 + tg) * 136 + mr + g];
                ah[1]  = Ah[(kc * 8 + tg) * 136 + mr + g + 8];
                ah[2]  = Ah[(kc * 8 + tg + 4) * 136 + mr + g];
                ah[3]  = Ah[(kc * 8 + tg + 4) * 136 + mr + g + 8];
                al_[0] = Al[(kc * 8 + tg) * 136 + mr + g];
                al_[1] = Al[(kc * 8 + tg) * 136 + mr + g + 8];
                al_[2] = Al[(kc * 8 + tg + 4) * 136 + mr + g];
                al_[3] = Al[(kc * 8 + tg + 4) * 136 + mr + g + 8];
                #pragma unroll
                for (int nt = 0; nt < 4; nt++) {
                    mma_bf16(acc[mt][nt], al_, bh[nt]);
                    mma_bf16(acc[mt][nt], ah,  bl[nt]);
                    mma_bf16(acc[mt][nt], ah,  bh[nt]);
                }
            }
        }
        __syncthreads();
    }

    #pragma unroll
    for (int mt = 0; mt < 4; mt++) {
        const int m = m0 + warp_m * 64 + mt * 16 + g;
        #pragma unroll
        for (int nt = 0; nt < 4; nt++) {
            const int n = n0 + warp_n * 32 + nt * 8 + 2 * tg;
            float a0 = acc[mt][nt][0], a1 = acc[mt][nt][1];
            float a2 = acc[mt][nt][2], a3 = acc[mt][nt][3];
            if (mode == 0) {
                const float b0 = bvec[n], b1 = bvec[n + 1];
                *(float2*)&C[(size_t)m * Ndim + n]       = make_float2(a0 + b0, a1 + b1);
                *(float2*)&C[(size_t)(m + 8) * Ndim + n] = make_float2(a2 + b0, a3 + b1);
            } else {
                const int seq = m & (SEQ - 1);
                const int bb  = m >> 11;
                if (n < 2 * EMB) {
                    const int d0 = n & (HD - 1);
                    const float* f0p = &freqs[(size_t)seq * HD + d0];
                    const float* f1p = f0p + (size_t)8 * HD;
                    float f0 = f0p[0], f1 = f0p[1];
                    float e0 = a0 * f0 - a1 * f1;
                    float e1 = a1 * f0 + a0 * f1;
                    float h0 = f1p[0], h1 = f1p[1];
                    float e2 = a2 * h0 - a3 * h1;
                    float e3 = a3 * h0 + a2 * h1;
                    if (n < EMB) {
                        *(float2*)&C[(size_t)m * EMB + n]       = make_float2(e0, e1);
                        *(float2*)&C[(size_t)(m + 8) * EMB + n] = make_float2(e2, e3);
                    } else {
                        const int hh = (n - EMB) >> 6;
                        const int d  = n & 63;
                        const int kt = seq >> 6, key = seq & 63;
                        uint32_t* dst = g_kvsp + ((size_t)(bb * HEADS + hh) * NKT + kt) * 8192;
                        uint32_t hp, lp;
                        split2(e0, e1, hp, lp);
                        *(uint2*)&dst[((d >> 1) * 64 + key) * 2] = make_uint2(hp, lp);
                        split2(e2, e3, hp, lp);
                        *(uint2*)&dst[((d >> 1) * 64 + key + 8) * 2] = make_uint2(hp, lp);
                    }
                } else {
                    const int hh = (n - 2 * EMB) >> 6;
                    const int d  = n & 63;
                    const int kt = seq >> 6, key = seq & 63;
                    uint32_t* dst = g_kvsp + ((size_t)(bb * HEADS + hh) * NKT + kt) * 8192 + 4096;
                    float p0 = __shfl_xor_sync(0xffffffffu, a0, 4);
                    float p1 = __shfl_xor_sync(0xffffffffu, a1, 4);
                    float p2 = __shfl_xor_sync(0xffffffffu, a2, 4);
                    float p3 = __shfl_xor_sync(0xffffffffu, a3, 4);
                    const int u0 = key >> 1;
                    uint32_t hp, lp;
                    if ((g & 1) == 0) {
                        split2(a0, p0, hp, lp);
                        *(uint2*)&dst[(u0 * 64 + d) * 2] = make_uint2(hp, lp);
                        split2(a2, p2, hp, lp);
                        *(uint2*)&dst[((u0 + 4) * 64 + d) * 2] = make_uint2(hp, lp);
                    } else {
                        split2(p1, a1, hp, lp);
                        *(uint2*)&dst[(u0 * 64 + d + 1) * 2] = make_uint2(hp, lp);
                        split2(p3, a3, hp, lp);
                        *(uint2*)&dst[((u0 + 4) * 64 + d + 1) * 2] = make_uint2(hp, lp);
                    }
                }
            }
        }
    }
}

// ---------------------------------------------------------------------------
// Flash attention: 4 warps x 32 q-rows (two m16 sub-blocks per warp).
// Each B-fragment (K or V) load feeds 6 mmas -> smem read volume per block
// halves vs round 11. 128 threads, __launch_bounds__(128,2) for 256 regs.
// ---------------------------------------------------------------------------
#define KSTG_W 4608
#define VOFF_W 9216

__device__ __forceinline__ void copy_tile128(const uint32_t* __restrict__ gsrc,
                                             uint32_t sbase_b, int tid)
{
    // 4096 words (32 rows x 128) -> smem pitch 144; 128 threads x 8 cp16
    #pragma unroll
    for (int i = 0; i < 8; i++) {
        const int q = tid + i * 128;
        const int r = q >> 5;
        const int c = (q & 31) * 4;
        cp16(sbase_b + (uint32_t)(r * 144 + c) * 4u, gsrc + r * 128 + c);
    }
}

__global__ __launch_bounds__(128, 2) void attn_kernel(const float* __restrict__ bias)
{
    extern __shared__ uint32_t sm[];
    uint32_t smb;
    {
        uint64_t t;
        asm("cvta.to.shared.u64 %0, %1;" : "=l"(t) : "l"(sm));
        smb = (uint32_t)t;
    }

    const int tid  = threadIdx.x;
    const int lane = tid & 31;
    const int w    = tid >> 5;       // warp 0..3
    const int g    = lane >> 2;
    const int tg   = lane & 3;
    const int q0   = blockIdx.x * 128;
    const int h    = blockIdx.y;
    const int b    = blockIdx.z;

    const int rowBase = q0 + w * 32 + g;     // mh block rows: rowBase+16*mh (+8)
    const float scale = 0.125f;
    const uint32_t* gtiles = g_kvsp + (size_t)(b * HEADS + h) * NKT * 8192;

    // Q fragments for both m-halves
    uint32_t qh[2][4][4], ql[2][4][4];
    #pragma unroll
    for (int mh = 0; mh < 2; mh++) {
        const float* qA = &g_q[(size_t)(b * SEQ + rowBase + mh * 16) * EMB + h * HD];
        const float* qB = qA + (size_t)8 * EMB;
        #pragma unroll
        for (int ks = 0; ks < 4; ks++) {
            const int d0 = ks * 16 + 2 * tg;
            float2 x0 = *(const float2*)&qA[d0];
            float2 x1 = *(const float2*)&qB[d0];
            float2 x2 = *(const float2*)&qA[d0 + 8];
            float2 x3 = *(const float2*)&qB[d0 + 8];
            split2(x0.x * scale, x0.y * scale, qh[mh][ks][0], ql[mh][ks][0]);
            split2(x1.x * scale, x1.y * scale, qh[mh][ks][1], ql[mh][ks][1]);
            split2(x2.x * scale, x2.y * scale, qh[mh][ks][2], ql[mh][ks][2]);
            split2(x3.x * scale, x3.y * scale, qh[mh][ks][3], ql[mh][ks][3]);
        }
    }

    float o[2][8][4];
    #pragma unroll
    for (int mh = 0; mh < 2; mh++)
        #pragma unroll
        for (int nb = 0; nb < 8; nb++)
            #pragma unroll
            for (int j = 0; j < 4; j++) o[mh][nb][j] = 0.0f;
    float mr[2][2] = {{-1e30f, -1e30f}, {-1e30f, -1e30f}};
    float lr[2][2] = {{0.f, 0.f}, {0.f, 0.f}};

    copy_tile128(gtiles, smb, tid);
    cp_commit();

    for (int kt = 0; kt < NKT; kt++) {
        const int cur = kt & 1;
        copy_tile128(gtiles + (size_t)kt * 8192 + 4096, smb + VOFF_W * 4, tid);  // V_t
        cp_commit();
        if (kt + 1 < NKT) {
            copy_tile128(gtiles + (size_t)(kt + 1) * 8192,
                         smb + (cur ^ 1) * (KSTG_W * 4), tid);                   // K_{t+1}
            cp_commit();
            asm volatile("cp.async.wait_group 2;");
        } else {
            asm volatile("cp.async.wait_group 1;");
        }
        __syncthreads();

        const uint32_t* Ks = sm + cur * KSTG_W;

        // S = Q @ K^T — one B load feeds both m-halves
        float s[2][8][4];
        #pragma unroll
        for (int mh = 0; mh < 2; mh++)
            #pragma unroll
            for (int nb = 0; nb < 8; nb++)
                #pragma unroll
                for (int j = 0; j < 4; j++) s[mh][nb][j] = 0.0f;

        #pragma unroll
        for (int ks = 0; ks < 4; ks++) {
            #pragma unroll
            for (int nb = 0; nb < 8; nb++) {
                uint2 w0 = *(const uint2*)&Ks[(8 * ks + tg) * 144 + (8 * nb + g) * 2];
                uint2 w1 = *(const uint2*)&Ks[(8 * ks + tg + 4) * 144 + (8 * nb + g) * 2];
                uint32_t bh[2] = {w0.x, w1.x};
                uint32_t bl[2] = {w0.y, w1.y};
                #pragma unroll
                for (int mh = 0; mh < 2; mh++) {
                    mma_bf16(s[mh][nb], ql[mh][ks], bh);
                    mma_bf16(s[mh][nb], qh[mh][ks], bl);
                    mma_bf16(s[mh][nb], qh[mh][ks], bh);
                }
            }
        }

        // bias + online softmax, per m-half
        #pragma unroll
        for (int mh = 0; mh < 2; mh++) {
            const float* bp = &bias[((size_t)h * SEQ + rowBase + mh * 16) * SEQ + kt * 64];
            float mx0 = -1e30f, mx1 = -1e30f;
            #pragma unroll
            for (int nb = 0; nb < 8; nb++) {
                float2 b0 = __ldcs((const float2*)(bp + nb * 8 + 2 * tg));
                float2 b1 = __ldcs((const float2*)(bp + (size_t)8 * SEQ + nb * 8 + 2 * tg));
                s[mh][nb][0] += b0.x; s[mh][nb][1] += b0.y;
                s[mh][nb][2] += b1.x; s[mh][nb][3] += b1.y;
                mx0 = fmaxf(mx0, fmaxf(s[mh][nb][0], s[mh][nb][1]));
                mx1 = fmaxf(mx1, fmaxf(s[mh][nb][2], s[mh][nb][3]));
            }
            mx0 = fmaxf(mx0, __shfl_xor_sync(0xffffffffu, mx0, 1));
            mx0 = fmaxf(mx0, __shfl_xor_sync(0xffffffffu, mx0, 2));
            mx1 = fmaxf(mx1, __shfl_xor_sync(0xffffffffu, mx1, 1));
            mx1 = fmaxf(mx1, __shfl_xor_sync(0xffffffffu, mx1, 2));
            const float nm0 = fmaxf(mr[mh][0], mx0), nm1 = fmaxf(mr[mh][1], mx1);
            const float al0 = __expf(mr[mh][0] - nm0), al1 = __expf(mr[mh][1] - nm1);
            mr[mh][0] = nm0; mr[mh][1] = nm1;

            float ts0 = 0.0f, ts1 = 0.0f;
            #pragma unroll
            for (int nb = 0; nb < 8; nb++) {
                s[mh][nb][0] = __expf(s[mh][nb][0] - nm0);
                s[mh][nb][1] = __expf(s[mh][nb][1] - nm0);
                s[mh][nb][2] = __expf(s[mh][nb][2] - nm1);
                s[mh][nb][3] = __expf(s[mh][nb][3] - nm1);
                ts0 += s[mh][nb][0] + s[mh][nb][1];
                ts1 += s[mh][nb][2] + s[mh][nb][3];
            }
            ts0 += __shfl_xor_sync(0xffffffffu, ts0, 1);
            ts0 += __shfl_xor_sync(0xffffffffu, ts0, 2);
            ts1 += __shfl_xor_sync(0xffffffffu, ts1, 1);
            ts1 += __shfl_xor_sync(0xffffffffu, ts1, 2);
            lr[mh][0] = lr[mh][0] * al0 + ts0;
            lr[mh][1] = lr[mh][1] * al1 + ts1;
            #pragma unroll
            for (int nb = 0; nb < 8; nb++) {
                o[mh][nb][0] *= al0; o[mh][nb][1] *= al0;
                o[mh][nb][2] *= al1; o[mh][nb][3] *= al1;
            }
        }

        if (kt + 1 < NKT) {
            asm volatile("cp.async.wait_group 1;");
        } else {
            asm volatile("cp.async.wait_group 0;");
        }
        __syncthreads();

        const uint32_t* Vs = sm + VOFF_W;

        // O += P @ V — one V load feeds both m-halves
        #pragma unroll
        for (int j = 0; j < 4; j++) {
            uint32_t ah[2][4], al_[2][4];
            #pragma unroll
            for (int mh = 0; mh < 2; mh++) {
                split2(s[mh][2 * j][0],     s[mh][2 * j][1],     ah[mh][0], al_[mh][0]);
                split2(s[mh][2 * j][2],     s[mh][2 * j][3],     ah[mh][1], al_[mh][1]);
                split2(s[mh][2 * j + 1][0], s[mh][2 * j + 1][1], ah[mh][2], al_[mh][2]);
                split2(s[mh][2 * j + 1][2], s[mh][2 * j + 1][3], ah[mh][3], al_[mh][3]);
            }
            #pragma unroll
            for (int nb = 0; nb < 8; nb++) {
                uint2 w0 = *(const uint2*)&Vs[(8 * j + tg) * 144 + (8 * nb + g) * 2];
                uint2 w1 = *(const uint2*)&Vs[(8 * j + tg + 4) * 144 + (8 * nb + g) * 2];
                uint32_t vh[2] = {w0.x, w1.x};
                uint32_t vl[2] = {w0.y, w1.y};
                #pragma unroll
                for (int mh = 0; mh < 2; mh++) {
                    mma_bf16(o[mh][nb], al_[mh], vh);
                    mma_bf16(o[mh][nb], ah[mh],  vl);
                    mma_bf16(o[mh][nb], ah[mh],  vh);
                }
            }
        }
        __syncthreads();
    }

    // epilogue: normalize + write pre-split proj-A operand
    #pragma unroll
    for (int mh = 0; mh < 2; mh++) {
        const float inv0 = 1.0f / lr[mh][0], inv1 = 1.0f / lr[mh][1];
        const int mA = b * SEQ + rowBase + mh * 16;
        #pragma unroll
        for (int nb = 0; nb < 8; nb++) {
            const int kp = h * 32 + nb * 4 + tg;
            uint32_t hh, ll;
            split2(o[mh][nb][0] * inv0, o[mh][nb][1] * inv0, hh, ll);
            g_ah[(size_t)kp * MROWS + mA] = hh;
            g_al[(size_t)kp * MROWS + mA] = ll;
            split2(o[mh][nb][2] * inv1, o[mh][nb][3] * inv1, hh, ll);
            g_ah[(size_t)kp * MROWS + mA + 8] = hh;
            g_al[(size_t)kp * MROWS + mA + 8] = ll;
        }
    }
}

// ---------------------------------------------------------------------------
extern "C" void kernel_launch(void* const* d_in, const int* in_sizes, int n_in,
                              void* d_out, int out_size)
{
    const float* x      = (const float*)d_in[0];
    const float* freqs  = (const float*)d_in[1];
    const float* bias   = (const float*)d_in[2];
    const float* w_qkv  = (const float*)d_in[3];
    const float* w_proj = (const float*)d_in[4];
    const float* b_proj = (const float*)d_in[5];
    float* out = (float*)d_out;

    float* q_ptr; cudaGetSymbolAddress((void**)&q_ptr, g_q);
    uint32_t *xh, *xl, *wqh, *wql, *wph, *wpl, *ah, *al;
    cudaGetSymbolAddress((void**)&xh,  g_xh);
    cudaGetSymbolAddress((void**)&xl,  g_xl);
    cudaGetSymbolAddress((void**)&wqh, g_wqh);
    cudaGetSymbolAddress((void**)&wql, g_wql);
    cudaGetSymbolAddress((void**)&wph, g_wph);
    cudaGetSymbolAddress((void**)&wpl, g_wpl);
    cudaGetSymbolAddress((void**)&ah,  g_ah);
    cudaGetSymbolAddress((void**)&al,  g_al);

    const int gemm_smem = 2 * 8704 * 4;     // 69632 B
    const int attn_smem = 13824 * 4;        // 55296 B
    cudaFuncSetAttribute(gemm_sp, cudaFuncAttributeMaxDynamicSharedMemorySize, gemm_smem);
    cudaFuncSetAttribute(attn_kernel, cudaFuncAttributeMaxDynamicSharedMemorySize, attn_smem);

    // attn is our 4th launch -> ncu capture slot
    prep_a<<<dim3(EMB / 32, MROWS / 64), 256>>>(x, xh, xl);                          // 1
    prep_w<<<dim3(QKVN / 512, EMB / 2), 128>>>(w_qkv, wqh, wql, QKVN);               // 2
    gemm_sp<<<dim3(QKVN / 128, MROWS / 128), 256, gemm_smem>>>(                      // 3
        xh, xl, wqh, wql, q_ptr, QKVN, freqs, nullptr, 1);
    attn_kernel<<<dim3(SEQ / 128, HEADS, BATCH), 128, attn_smem>>>(bias);            // 4 <- profiled
    prep_w<<<dim3(EMB / 512, EMB / 2), 128>>>(w_proj, wph, wpl, EMB);                // 5
    gemm_sp<<<dim3(EMB / 128, MROWS / 128), 256, gemm_smem>>>(                       // 6
        ah, al, wph, wpl, out, EMB, nullptr, b_proj, 0);
}

// round 13
// speedup vs baseline: 1.0002x; 1.0002x over previous
#include <cuda_runtime.h>
#include <cuda_bf16.h>
#include <cstdint>

#define BATCH 2
#define SEQ   2048
#define HEADS 16
#define HD    64
#define EMB   1024
#define MROWS (BATCH*SEQ)
#define QKVN  (3*EMB)
#define NKT   (SEQ/64)           // 32 key tiles

// roped q, fp32 dense [MROWS][EMB]
__device__ float g_q[(size_t)MROWS * EMB];                               // 16.8 MB
// K/V tiles, {hi,lo}-interleaved bf16x2 words (round-11 layout)
__device__ uint32_t g_kvsp[(size_t)BATCH * HEADS * NKT * 8192];          // 67.1 MB
// Pre-split GEMM operands, {hi,lo} INTERLEAVED:
//   word index = (kp * (M|N) + pos) * 2 + {0:hi, 1:lo}
__device__ uint32_t g_xi[(size_t)(EMB/2) * MROWS * 2];
__device__ uint32_t g_wqi[(size_t)(EMB/2) * QKVN * 2];
__device__ uint32_t g_wpi[(size_t)(EMB/2) * EMB * 2];
__device__ uint32_t g_ai[(size_t)(EMB/2) * MROWS * 2];

__device__ __forceinline__ uint32_t pack_bf16x2(float e0, float e1) {
    uint32_t r;
    asm("cvt.rn.bf16x2.f32 %0, %1, %2;" : "=r"(r) : "f"(e1), "f"(e0));
    return r;
}
__device__ __forceinline__ void split2(float x, float y, uint32_t& hp, uint32_t& lp) {
    float hx = __bfloat162float(__float2bfloat16_rn(x));
    float hy = __bfloat162float(__float2bfloat16_rn(y));
    hp = pack_bf16x2(hx, hy);
    lp = pack_bf16x2(x - hx, y - hy);
}
__device__ __forceinline__ void mma_bf16(float c[4], const uint32_t a[4], const uint32_t b[2]) {
    asm volatile(
        "mma.sync.aligned.m16n8k16.row.col.f32.bf16.bf16.f32 "
        "{%0,%1,%2,%3}, {%4,%5,%6,%7}, {%8,%9}, {%0,%1,%2,%3};"
        : "+f"(c[0]), "+f"(c[1]), "+f"(c[2]), "+f"(c[3])
        : "r"(a[0]), "r"(a[1]), "r"(a[2]), "r"(a[3]), "r"(b[0]), "r"(b[1]));
}
__device__ __forceinline__ void cp16(uint32_t dst, const void* src) {
    asm volatile("cp.async.cg.shared.global [%0], [%1], 16;" :: "r"(dst), "l"(src));
}
__device__ __forceinline__ void cp_commit() {
    asm volatile("cp.async.commit_group;");
}

// ---------------------------------------------------------------------------
// prep_a: split fp32 A[M][K] into interleaved {hi,lo} [kp][M][2]
// ---------------------------------------------------------------------------
__global__ __launch_bounds__(256) void prep_a(const float* __restrict__ A,
                                              uint32_t* __restrict__ di)
{
    __shared__ float stage[64 * 33];
    const int tid = threadIdx.x;
    const int k0 = blockIdx.x * 32;
    const int m0 = blockIdx.y * 64;

    #pragma unroll
    for (int j = 0; j < 2; j++) {
        const int f = tid + j * 256;
        const int r = f >> 3;
        const int c4 = (f & 7) * 4;
        float4 v = *(const float4*)&A[(size_t)(m0 + r) * EMB + k0 + c4];
        stage[r * 33 + c4 + 0] = v.x;
        stage[r * 33 + c4 + 1] = v.y;
        stage[r * 33 + c4 + 2] = v.z;
        stage[r * 33 + c4 + 3] = v.w;
    }
    __syncthreads();

    const int m_l = tid & 63;
    #pragma unroll
    for (int j = 0; j < 4; j++) {
        const int kp_l = (tid >> 6) + j * 4;
        float a = stage[m_l * 33 + 2 * kp_l];
        float b = stage[m_l * 33 + 2 * kp_l + 1];
        uint32_t h, l;
        split2(a, b, h, l);
        *(uint2*)&di[((size_t)(k0 / 2 + kp_l) * MROWS + m0 + m_l) * 2] = make_uint2(h, l);
    }
}

// ---------------------------------------------------------------------------
// prep_w: split fp32 W[K][N] into interleaved {hi,lo} [kp][N][2]
// ---------------------------------------------------------------------------
__global__ __launch_bounds__(128) void prep_w(const float* __restrict__ W,
                                              uint32_t* __restrict__ di, int N)
{
    const int n  = blockIdx.x * 512 + threadIdx.x * 4;
    const int kp = blockIdx.y;
    float4 r0 = *(const float4*)&W[(size_t)(2 * kp) * N + n];
    float4 r1 = *(const float4*)&W[(size_t)(2 * kp + 1) * N + n];
    uint32_t h[4], l[4];
    split2(r0.x, r1.x, h[0], l[0]);
    split2(r0.y, r1.y, h[1], l[1]);
    split2(r0.z, r1.z, h[2], l[2]);
    split2(r0.w, r1.w, h[3], l[3]);
    uint32_t* dst = &di[((size_t)kp * N + n) * 2];
    *(uint4*)&dst[0] = make_uint4(h[0], l[0], h[1], l[1]);
    *(uint4*)&dst[4] = make_uint4(h[2], l[2], h[3], l[3]);
}

// ---------------------------------------------------------------------------
// 3xBF16 GEMM, interleaved {hi,lo} operands -> LDS.64 fragment loads.
// BM=128 BN=128 BK=32, 256 threads / 8 warps, warp tile 64x32.
// smem per stage (u32 words): A 16 rows x 264 pitch (256 data + 8 pad),
// B same; stage = 8448 words. Two stages = 67584 B.
// ---------------------------------------------------------------------------
#define GSTG_W 8448
__global__ __launch_bounds__(256, 2) void gemm_sp(
    const uint32_t* __restrict__ AiG, const uint32_t* __restrict__ BiG,
    float* __restrict__ C, int Ndim,
    const float* __restrict__ freqs,
    const float* __restrict__ bvec, int mode)
{
    extern __shared__ uint32_t sm[];
    uint32_t smb;
    {
        uint64_t t;
        asm("cvta.to.shared.u64 %0, %1;" : "=l"(t) : "l"(sm));
        smb = (uint32_t)t;
    }

    const int tid  = threadIdx.x;
    const int lane = tid & 31;
    const int warp = tid >> 5;
    const int g    = lane >> 2;
    const int tg   = lane & 3;
    const int warp_m = warp >> 2;
    const int warp_n = warp & 3;
    const int m0 = blockIdx.y * 128;
    const int n0 = blockIdx.x * 128;

    float acc[4][4][4];
    #pragma unroll
    for (int mt = 0; mt < 4; mt++)
        #pragma unroll
        for (int nt = 0; nt < 4; nt++)
            #pragma unroll
            for (int c = 0; c < 4; c++) acc[mt][nt][c] = 0.0f;

    // loader: 2048 16B segments per stage; f = tid + i*256
    //   half = f>>10 (0=A,1=B), r = (f>>6)&15, seg = f&63
    {
        #pragma unroll
        for (int i = 0; i < 8; i++) {
            const int f = tid + i * 256;
            const int half = f >> 10, r = (f >> 6) & 15, seg = f & 63;
            const uint32_t* src = (half == 0)
                ? AiG + ((size_t)r * MROWS + m0) * 2 + seg * 4
                : BiG + ((size_t)r * Ndim + n0) * 2 + seg * 4;
            cp16(smb + (uint32_t)(half * 4224 + r * 264 + seg * 4) * 4u, src);
        }
        cp_commit();
    }

    const int NIT = EMB / 32;
    for (int it = 0; it < NIT; it++) {
        const int cur = it & 1;
        if (it + 1 < NIT) {
            const int kp0 = (it + 1) * 16;
            const uint32_t sb = smb + (uint32_t)((cur ^ 1) * GSTG_W) * 4u;
            #pragma unroll
            for (int i = 0; i < 8; i++) {
                const int f = tid + i * 256;
                const int half = f >> 10, r = (f >> 6) & 15, seg = f & 63;
                const uint32_t* src = (half == 0)
                    ? AiG + ((size_t)(kp0 + r) * MROWS + m0) * 2 + seg * 4
                    : BiG + ((size_t)(kp0 + r) * Ndim + n0) * 2 + seg * 4;
                cp16(sb + (uint32_t)(half * 4224 + r * 264 + seg * 4) * 4u, src);
            }
            cp_commit();
            asm volatile("cp.async.wait_group 1;");
        } else {
            asm volatile("cp.async.wait_group 0;");
        }
        __syncthreads();

        const uint32_t* As = sm + cur * GSTG_W;
        const uint32_t* Bs = As + 4224;

        #pragma unroll
        for (int kc = 0; kc < 2; kc++) {
            uint32_t bh[4][2], bl[4][2];
            #pragma unroll
            for (int nt = 0; nt < 4; nt++) {
                const int nc = warp_n * 32 + nt * 8 + g;
                uint2 w0 = *(const uint2*)&Bs[(kc * 8 + tg) * 264 + nc * 2];
                uint2 w1 = *(const uint2*)&Bs[(kc * 8 + tg + 4) * 264 + nc * 2];
                bh[nt][0] = w0.x; bl[nt][0] = w0.y;
                bh[nt][1] = w1.x; bl[nt][1] = w1.y;
            }
            #pragma unroll
            for (int mt = 0; mt < 4; mt++) {
                const int mr = warp_m * 64 + mt * 16;
                uint2 a0 = *(const uint2*)&As[(kc * 8 + tg) * 264 + (mr + g) * 2];
                uint2 a1 = *(const uint2*)&As[(kc * 8 + tg) * 264 + (mr + g + 8) * 2];
                uint2 a2 = *(const uint2*)&As[(kc * 8 + tg + 4) * 264 + (mr + g) * 2];
                uint2 a3 = *(const uint2*)&As[(kc * 8 + tg + 4) * 264 + (mr + g + 8) * 2];
                uint32_t ah[4]  = {a0.x, a1.x, a2.x, a3.x};
                uint32_t al_[4] = {a0.y, a1.y, a2.y, a3.y};
                #pragma unroll
                for (int nt = 0; nt < 4; nt++) {
                    mma_bf16(acc[mt][nt], al_, bh[nt]);
                    mma_bf16(acc[mt][nt], ah,  bl[nt]);
                    mma_bf16(acc[mt][nt], ah,  bh[nt]);
                }
            }
        }
        __syncthreads();
    }

    // epilogue (mode 1: RoPE + scatter; mode 0: +bias)
    #pragma unroll
    for (int mt = 0; mt < 4; mt++) {
        const int m = m0 + warp_m * 64 + mt * 16 + g;
        #pragma unroll
        for (int nt = 0; nt < 4; nt++) {
            const int n = n0 + warp_n * 32 + nt * 8 + 2 * tg;
            float a0 = acc[mt][nt][0], a1 = acc[mt][nt][1];
            float a2 = acc[mt][nt][2], a3 = acc[mt][nt][3];
            if (mode == 0) {
                const float b0 = bvec[n], b1 = bvec[n + 1];
                *(float2*)&C[(size_t)m * Ndim + n]       = make_float2(a0 + b0, a1 + b1);
                *(float2*)&C[(size_t)(m + 8) * Ndim + n] = make_float2(a2 + b0, a3 + b1);
            } else {
                const int seq = m & (SEQ - 1);
                const int bb  = m >> 11;
                if (n < 2 * EMB) {
                    const int d0 = n & (HD - 1);
                    const float* f0p = &freqs[(size_t)seq * HD + d0];
                    const float* f1p = f0p + (size_t)8 * HD;
                    float f0 = f0p[0], f1 = f0p[1];
                    float e0 = a0 * f0 - a1 * f1;
                    float e1 = a1 * f0 + a0 * f1;
                    float h0 = f1p[0], h1 = f1p[1];
                    float e2 = a2 * h0 - a3 * h1;
                    float e3 = a3 * h0 + a2 * h1;
                    if (n < EMB) {
                        *(float2*)&C[(size_t)m * EMB + n]       = make_float2(e0, e1);
                        *(float2*)&C[(size_t)(m + 8) * EMB + n] = make_float2(e2, e3);
                    } else {
                        const int hh = (n - EMB) >> 6;
                        const int d  = n & 63;
                        const int kt = seq >> 6, key = seq & 63;
                        uint32_t* dst = g_kvsp + ((size_t)(bb * HEADS + hh) * NKT + kt) * 8192;
                        uint32_t hp, lp;
                        split2(e0, e1, hp, lp);
                        *(uint2*)&dst[((d >> 1) * 64 + key) * 2] = make_uint2(hp, lp);
                        split2(e2, e3, hp, lp);
                        *(uint2*)&dst[((d >> 1) * 64 + key + 8) * 2] = make_uint2(hp, lp);
                    }
                } else {
                    const int hh = (n - 2 * EMB) >> 6;
                    const int d  = n & 63;
                    const int kt = seq >> 6, key = seq & 63;
                    uint32_t* dst = g_kvsp + ((size_t)(bb * HEADS + hh) * NKT + kt) * 8192 + 4096;
                    float p0 = __shfl_xor_sync(0xffffffffu, a0, 4);
                    float p1 = __shfl_xor_sync(0xffffffffu, a1, 4);
                    float p2 = __shfl_xor_sync(0xffffffffu, a2, 4);
                    float p3 = __shfl_xor_sync(0xffffffffu, a3, 4);
                    const int u0 = key >> 1;
                    uint32_t hp, lp;
                    if ((g & 1) == 0) {
                        split2(a0, p0, hp, lp);
                        *(uint2*)&dst[(u0 * 64 + d) * 2] = make_uint2(hp, lp);
                        split2(a2, p2, hp, lp);
                        *(uint2*)&dst[((u0 + 4) * 64 + d) * 2] = make_uint2(hp, lp);
                    } else {
                        split2(p1, a1, hp, lp);
                        *(uint2*)&dst[(u0 * 64 + d + 1) * 2] = make_uint2(hp, lp);
                        split2(p3, a3, hp, lp);
                        *(uint2*)&dst[((u0 + 4) * 64 + d + 1) * 2] = make_uint2(hp, lp);
                    }
                }
            }
        }
    }
}

// ---------------------------------------------------------------------------
// Flash attention — exact round-11 core (454us), epilogue writes interleaved
// proj-A operand.
// ---------------------------------------------------------------------------
#define KSTG_W 4608
#define VOFF_W 9216

__device__ __forceinline__ void copy_tile(const uint32_t* __restrict__ gsrc,
                                          uint32_t sbase_b, int tid)
{
    #pragma unroll
    for (int i = 0; i < 4; i++) {
        const int q = tid + i * 256;
        const int r = q >> 5;
        const int c = (q & 31) * 4;
        cp16(sbase_b + (uint32_t)(r * 144 + c) * 4u, gsrc + r * 128 + c);
    }
}

__global__ __launch_bounds__(256, 2) void attn_kernel(const float* __restrict__ bias)
{
    extern __shared__ uint32_t sm[];
    uint32_t smb;
    {
        uint64_t t;
        asm("cvta.to.shared.u64 %0, %1;" : "=l"(t) : "l"(sm));
        smb = (uint32_t)t;
    }

    const int tid  = threadIdx.x;
    const int lane = tid & 31;
    const int w    = tid >> 5;
    const int g    = lane >> 2;
    const int tg   = lane & 3;
    const int q0   = blockIdx.x * 128;
    const int h    = blockIdx.y;
    const int b    = blockIdx.z;

    const int rowA = q0 + w * 16 + g;
    const float scale = 0.125f;
    const uint32_t* gtiles = g_kvsp + (size_t)(b * HEADS + h) * NKT * 8192;

    uint32_t qh[4][4], ql[4][4];
    {
        const float* qA = &g_q[(size_t)(b * SEQ + rowA) * EMB + h * HD];
        const float* qB = qA + (size_t)8 * EMB;
        #pragma unroll
        for (int ks = 0; ks < 4; ks++) {
            const int d0 = ks * 16 + 2 * tg;
            float2 x0 = *(const float2*)&qA[d0];
            float2 x1 = *(const float2*)&qB[d0];
            float2 x2 = *(const float2*)&qA[d0 + 8];
            float2 x3 = *(const float2*)&qB[d0 + 8];
            split2(x0.x * scale, x0.y * scale, qh[ks][0], ql[ks][0]);
            split2(x1.x * scale, x1.y * scale, qh[ks][1], ql[ks][1]);
            split2(x2.x * scale, x2.y * scale, qh[ks][2], ql[ks][2]);
            split2(x3.x * scale, x3.y * scale, qh[ks][3], ql[ks][3]);
        }
    }

    float o[8][4];
    #pragma unroll
    for (int nb = 0; nb < 8; nb++)
        #pragma unroll
        for (int j = 0; j < 4; j++) o[nb][j] = 0.0f;
    float m0 = -1e30f, m1 = -1e30f, l0 = 0.0f, l1 = 0.0f;

    copy_tile(gtiles, smb, tid);
    cp_commit();

    for (int kt = 0; kt < NKT; kt++) {
        const int cur = kt & 1;
        copy_tile(gtiles + (size_t)kt * 8192 + 4096, smb + VOFF_W * 4, tid);
        cp_commit();
        if (kt + 1 < NKT) {
            copy_tile(gtiles + (size_t)(kt + 1) * 8192,
                      smb + (cur ^ 1) * (KSTG_W * 4), tid);
            cp_commit();
            asm volatile("cp.async.wait_group 2;");
        } else {
            asm volatile("cp.async.wait_group 1;");
        }
        __syncthreads();

        const uint32_t* Ks = sm + cur * KSTG_W;

        float s[8][4];
        #pragma unroll
        for (int nb = 0; nb < 8; nb++)
            #pragma unroll
            for (int j = 0; j < 4; j++) s[nb][j] = 0.0f;

        #pragma unroll
        for (int ks = 0; ks < 4; ks++) {
            #pragma unroll
            for (int nb = 0; nb < 8; nb++) {
                uint2 w0 = *(const uint2*)&Ks[(8 * ks + tg) * 144 + (8 * nb + g) * 2];
                uint2 w1 = *(const uint2*)&Ks[(8 * ks + tg + 4) * 144 + (8 * nb + g) * 2];
                uint32_t bh[2] = {w0.x, w1.x};
                uint32_t bl[2] = {w0.y, w1.y};
                mma_bf16(s[nb], ql[ks], bh);
                mma_bf16(s[nb], qh[ks], bl);
                mma_bf16(s[nb], qh[ks], bh);
            }
        }

        const float* bp = &bias[((size_t)h * SEQ + rowA) * SEQ + kt * 64];
        float mx0 = -1e30f, mx1 = -1e30f;
        #pragma unroll
        for (int nb = 0; nb < 8; nb++) {
            float2 b0 = __ldcs((const float2*)(bp + nb * 8 + 2 * tg));
            float2 b1 = __ldcs((const float2*)(bp + (size_t)8 * SEQ + nb * 8 + 2 * tg));
            s[nb][0] += b0.x; s[nb][1] += b0.y;
            s[nb][2] += b1.x; s[nb][3] += b1.y;
            mx0 = fmaxf(mx0, fmaxf(s[nb][0], s[nb][1]));
            mx1 = fmaxf(mx1, fmaxf(s[nb][2], s[nb][3]));
        }
        mx0 = fmaxf(mx0, __shfl_xor_sync(0xffffffffu, mx0, 1));
        mx0 = fmaxf(mx0, __shfl_xor_sync(0xffffffffu, mx0, 2));
        mx1 = fmaxf(mx1, __shfl_xor_sync(0xffffffffu, mx1, 1));
        mx1 = fmaxf(mx1, __shfl_xor_sync(0xffffffffu, mx1, 2));
        const float nm0 = fmaxf(m0, mx0), nm1 = fmaxf(m1, mx1);
        const float al0 = __expf(m0 - nm0), al1 = __expf(m1 - nm1);
        m0 = nm0; m1 = nm1;

        float ts0 = 0.0f, ts1 = 0.0f;
        #pragma unroll
        for (int nb = 0; nb < 8; nb++) {
            s[nb][0] = __expf(s[nb][0] - nm0);
            s[nb][1] = __expf(s[nb][1] - nm0);
            s[nb][2] = __expf(s[nb][2] - nm1);
            s[nb][3] = __expf(s[nb][3] - nm1);
            ts0 += s[nb][0] + s[nb][1];
            ts1 += s[nb][2] + s[nb][3];
        }
        ts0 += __shfl_xor_sync(0xffffffffu, ts0, 1);
        ts0 += __shfl_xor_sync(0xffffffffu, ts0, 2);
        ts1 += __shfl_xor_sync(0xffffffffu, ts1, 1);
        ts1 += __shfl_xor_sync(0xffffffffu, ts1, 2);
        l0 = l0 * al0 + ts0;
        l1 = l1 * al1 + ts1;
        #pragma unroll
        for (int nb = 0; nb < 8; nb++) {
            o[nb][0] *= al0; o[nb][1] *= al0;
            o[nb][2] *= al1; o[nb][3] *= al1;
        }

        if (kt + 1 < NKT) {
            asm volatile("cp.async.wait_group 1;");
        } else {
            asm volatile("cp.async.wait_group 0;");
        }
        __syncthreads();

        const uint32_t* Vs = sm + VOFF_W;

        #pragma unroll
        for (int j = 0; j < 4; j++) {
            uint32_t ah[4], al_[4];
            split2(s[2 * j][0],     s[2 * j][1],     ah[0], al_[0]);
            split2(s[2 * j][2],     s[2 * j][3],     ah[1], al_[1]);
            split2(s[2 * j + 1][0], s[2 * j + 1][1], ah[2], al_[2]);
            split2(s[2 * j + 1][2], s[2 * j + 1][3], ah[3], al_[3]);
            #pragma unroll
            for (int nb = 0; nb < 8; nb++) {
                uint2 w0 = *(const uint2*)&Vs[(8 * j + tg) * 144 + (8 * nb + g) * 2];
                uint2 w1 = *(const uint2*)&Vs[(8 * j + tg + 4) * 144 + (8 * nb + g) * 2];
                uint32_t vh[2] = {w0.x, w1.x};
                uint32_t vl[2] = {w0.y, w1.y};
                mma_bf16(o[nb], al_, vh);
                mma_bf16(o[nb], ah,  vl);
                mma_bf16(o[nb], ah,  vh);
            }
        }
        __syncthreads();
    }

    // epilogue: normalize + write interleaved proj-A operand
    const float inv0 = 1.0f / l0, inv1 = 1.0f / l1;
    const int mA = b * SEQ + rowA;
    #pragma unroll
    for (int nb = 0; nb < 8; nb++) {
        const int kp = h * 32 + nb * 4 + tg;
        uint32_t hh, ll;
        split2(o[nb][0] * inv0, o[nb][1] * inv0, hh, ll);
        *(uint2*)&g_ai[((size_t)kp * MROWS + mA) * 2] = make_uint2(hh, ll);
        split2(o[nb][2] * inv1, o[nb][3] * inv1, hh, ll);
        *(uint2*)&g_ai[((size_t)kp * MROWS + mA + 8) * 2] = make_uint2(hh, ll);
    }
}

// ---------------------------------------------------------------------------
extern "C" void kernel_launch(void* const* d_in, const int* in_sizes, int n_in,
                              void* d_out, int out_size)
{
    const float* x      = (const float*)d_in[0];
    const float* freqs  = (const float*)d_in[1];
    const float* bias   = (const float*)d_in[2];
    const float* w_qkv  = (const float*)d_in[3];
    const float* w_proj = (const float*)d_in[4];
    const float* b_proj = (const float*)d_in[5];
    float* out = (float*)d_out;

    float* q_ptr; cudaGetSymbolAddress((void**)&q_ptr, g_q);
    uint32_t *xi, *wqi, *wpi, *ai;
    cudaGetSymbolAddress((void**)&xi,  g_xi);
    cudaGetSymbolAddress((void**)&wqi, g_wqi);
    cudaGetSymbolAddress((void**)&wpi, g_wpi);
    cudaGetSymbolAddress((void**)&ai,  g_ai);

    const int gemm_smem = 2 * GSTG_W * 4;   // 67584 B
    const int attn_smem = 13824 * 4;        // 55296 B
    cudaFuncSetAttribute(gemm_sp, cudaFuncAttributeMaxDynamicSharedMemorySize, gemm_smem);
    cudaFuncSetAttribute(attn_kernel, cudaFuncAttributeMaxDynamicSharedMemorySize, attn_smem);

    // QKV gemm is our 4th launch -> ncu capture slot
    prep_a<<<dim3(EMB / 32, MROWS / 64), 256>>>(x, xi);                              // 1
    prep_w<<<dim3(QKVN / 512, EMB / 2), 128>>>(w_qkv, wqi, QKVN);                    // 2
    prep_w<<<dim3(EMB / 512, EMB / 2), 128>>>(w_proj, wpi, EMB);                     // 3
    gemm_sp<<<dim3(QKVN / 128, MROWS / 128), 256, gemm_smem>>>(                      // 4 <- profiled
        xi, wqi, q_ptr, QKVN, freqs, nullptr, 1);
    attn_kernel<<<dim3(SEQ / 128, HEADS, BATCH), 256, attn_smem>>>(bias);            // 5
    gemm_sp<<<dim3(EMB / 128, MROWS / 128), 256, gemm_smem>>>(                       // 6
        ai, wpi, out, EMB, nullptr, b_proj, 0);
}

// round 15
// speedup vs baseline: 1.1334x; 1.1332x over previous
#include <cuda_runtime.h>
#include <cuda_bf16.h>
#include <cstdint>

#define BATCH 2
#define SEQ   2048
#define HEADS 16
#define HD    64
#define EMB   1024
#define MROWS (BATCH*SEQ)
#define QKVN  (3*EMB)
#define NKT   (SEQ/64)           // 32 key tiles

// roped q, fp32 dense [MROWS][EMB]
__device__ float g_q[(size_t)MROWS * EMB];                               // 16.8 MB
// K/V tiles, {hi,lo}-interleaved bf16x2 words (r11 layout):
//   per (b,h,kt) tile 8192 words: K at 0:   ((d/2)*64 + key)*2 + {0,1}
//                                 V at 4096: ((key/2)*64 + d)*2 + {0,1}
__device__ uint32_t g_kvsp[(size_t)BATCH * HEADS * NKT * 8192];          // 67.1 MB
// Pre-split GEMM operands (separate hi/lo): [kp][M or N]
__device__ uint32_t g_xh[(size_t)(EMB/2) * MROWS],  g_xl[(size_t)(EMB/2) * MROWS];
__device__ uint32_t g_wqh[(size_t)(EMB/2) * QKVN],  g_wql[(size_t)(EMB/2) * QKVN];
__device__ uint32_t g_wph[(size_t)(EMB/2) * EMB],   g_wpl[(size_t)(EMB/2) * EMB];
__device__ uint32_t g_ah[(size_t)(EMB/2) * MROWS],  g_al[(size_t)(EMB/2) * MROWS];

__device__ __forceinline__ uint32_t pack_bf16x2(float e0, float e1) {
    uint32_t r;
    asm("cvt.rn.bf16x2.f32 %0, %1, %2;" : "=r"(r) : "f"(e1), "f"(e0));
    return r;
}
__device__ __forceinline__ void split2(float x, float y, uint32_t& hp, uint32_t& lp) {
    float hx = __bfloat162float(__float2bfloat16_rn(x));
    float hy = __bfloat162float(__float2bfloat16_rn(y));
    hp = pack_bf16x2(hx, hy);
    lp = pack_bf16x2(x - hx, y - hy);
}
__device__ __forceinline__ void mma_bf16(float c[4], const uint32_t a[4], const uint32_t b[2]) {
    asm volatile(
        "mma.sync.aligned.m16n8k16.row.col.f32.bf16.bf16.f32 "
        "{%0,%1,%2,%3}, {%4,%5,%6,%7}, {%8,%9}, {%0,%1,%2,%3};"
        : "+f"(c[0]), "+f"(c[1]), "+f"(c[2]), "+f"(c[3])
        : "r"(a[0]), "r"(a[1]), "r"(a[2]), "r"(a[3]), "r"(b[0]), "r"(b[1]));
}
__device__ __forceinline__ void cp16(uint32_t dst, const void* src) {
    asm volatile("cp.async.cg.shared.global [%0], [%1], 16;" :: "r"(dst), "l"(src));
}
__device__ __forceinline__ void cp_commit() {
    asm volatile("cp.async.commit_group;");
}

// ---------------------------------------------------------------------------
// prep_a: split fp32 A[M][K] into Ah/Al[kp][M] via smem transpose (r11)
// ---------------------------------------------------------------------------
__global__ __launch_bounds__(256) void prep_a(const float* __restrict__ A,
                                              uint32_t* __restrict__ dh,
                                              uint32_t* __restrict__ dl)
{
    __shared__ float stage[64 * 33];
    const int tid = threadIdx.x;
    const int k0 = blockIdx.x * 32;
    const int m0 = blockIdx.y * 64;

    #pragma unroll
    for (int j = 0; j < 2; j++) {
        const int f = tid + j * 256;
        const int r = f >> 3;
        const int c4 = (f & 7) * 4;
        float4 v = *(const float4*)&A[(size_t)(m0 + r) * EMB + k0 + c4];
        stage[r * 33 + c4 + 0] = v.x;
        stage[r * 33 + c4 + 1] = v.y;
        stage[r * 33 + c4 + 2] = v.z;
        stage[r * 33 + c4 + 3] = v.w;
    }
    __syncthreads();

    const int m_l = tid & 63;
    #pragma unroll
    for (int j = 0; j < 4; j++) {
        const int kp_l = (tid >> 6) + j * 4;
        float a = stage[m_l * 33 + 2 * kp_l];
        float b = stage[m_l * 33 + 2 * kp_l + 1];
        uint32_t h, l;
        split2(a, b, h, l);
        dh[(size_t)(k0 / 2 + kp_l) * MROWS + m0 + m_l] = h;
        dl[(size_t)(k0 / 2 + kp_l) * MROWS + m0 + m_l] = l;
    }
}

// ---------------------------------------------------------------------------
// prep_w: split fp32 W[K][N] into Wh/Wl[kp][N] (r11)
// ---------------------------------------------------------------------------
__global__ __launch_bounds__(128) void prep_w(const float* __restrict__ W,
                                              uint32_t* __restrict__ dh,
                                              uint32_t* __restrict__ dl, int N)
{
    const int n  = blockIdx.x * 512 + threadIdx.x * 4;
    const int kp = blockIdx.y;
    float4 r0 = *(const float4*)&W[(size_t)(2 * kp) * N + n];
    float4 r1 = *(const float4*)&W[(size_t)(2 * kp + 1) * N + n];
    uint32_t h[4], l[4];
    split2(r0.x, r1.x, h[0], l[0]);
    split2(r0.y, r1.y, h[1], l[1]);
    split2(r0.z, r1.z, h[2], l[2]);
    split2(r0.w, r1.w, h[3], l[3]);
    *(uint4*)&dh[(size_t)kp * N + n] = make_uint4(h[0], h[1], h[2], h[3]);
    *(uint4*)&dl[(size_t)kp * N + n] = make_uint4(l[0], l[1], l[2], l[3]);
}

// ---------------------------------------------------------------------------
// 3xBF16 GEMM (r11 core), restructured k-loop: ONE barrier per iteration.
// Per iter: wait(tile it resident) -> sync -> issue prefetch(it+1) -> compute.
// Prefetch writes stage cur^1, whose readers (iter it-1) all passed this
// iteration's syncthreads.
// ---------------------------------------------------------------------------
__global__ __launch_bounds__(256, 2) void gemm_sp(
    const uint32_t* __restrict__ AhG, const uint32_t* __restrict__ AlG,
    const uint32_t* __restrict__ BhG, const uint32_t* __restrict__ BlG,
    float* __restrict__ C, int Ndim,
    const float* __restrict__ freqs,
    const float* __restrict__ bvec, int mode)
{
    extern __shared__ uint32_t sm[];
    uint32_t smb;
    {
        uint64_t t;
        asm("cvta.to.shared.u64 %0, %1;" : "=l"(t) : "l"(sm));
        smb = (uint32_t)t;
    }

    const int tid  = threadIdx.x;
    const int lane = tid & 31;
    const int warp = tid >> 5;
    const int g    = lane >> 2;
    const int tg   = lane & 3;
    const int warp_m = warp >> 2;
    const int warp_n = warp & 3;
    const int m0 = blockIdx.y * 128;
    const int n0 = blockIdx.x * 128;

    float acc[4][4][4];
    #pragma unroll
    for (int mt = 0; mt < 4; mt++)
        #pragma unroll
        for (int nt = 0; nt < 4; nt++)
            #pragma unroll
            for (int c = 0; c < 4; c++) acc[mt][nt][c] = 0.0f;

    const uint32_t* gArr[4] = {AhG, AlG, BhG, BlG};

    // prologue: tile 0 -> stage 0
    {
        #pragma unroll
        for (int i = 0; i < 8; i++) {
            const int f = tid + i * 256;
            const int arr = f >> 9, r = (f >> 5) & 15, seg = f & 31;
            const uint32_t* src = (arr < 2)
                ? gArr[arr] + (size_t)r * MROWS + m0 + seg * 4
                : gArr[arr] + (size_t)r * Ndim + n0 + seg * 4;
            cp16(smb + (uint32_t)(arr * 2176 + r * 136 + seg * 4) * 4u, src);
        }
        cp_commit();
    }

    const int NIT = EMB / 32;
    for (int it = 0; it < NIT; it++) {
        const int cur = it & 1;
        asm volatile("cp.async.wait_group 0;");   // tile it resident
        __syncthreads();                          // visible to all; prior reads done
        if (it + 1 < NIT) {
            const int kp0 = (it + 1) * 16;
            const uint32_t sb = smb + (uint32_t)((cur ^ 1) * 8704) * 4u;
            #pragma unroll
            for (int i = 0; i < 8; i++) {
                const int f = tid + i * 256;
                const int arr = f >> 9, r = (f >> 5) & 15, seg = f & 31;
                const uint32_t* src = (arr < 2)
                    ? gArr[arr] + (size_t)(kp0 + r) * MROWS + m0 + seg * 4
                    : gArr[arr] + (size_t)(kp0 + r) * Ndim + n0 + seg * 4;
                cp16(sb + (uint32_t)(arr * 2176 + r * 136 + seg * 4) * 4u, src);
            }
            cp_commit();
        }

        const uint32_t* Ah = sm + cur * 8704;
        const uint32_t* Al = Ah + 2176;
        const uint32_t* Bh = Ah + 4352;
        const uint32_t* Bl = Ah + 6528;

        #pragma unroll
        for (int kc = 0; kc < 2; kc++) {
            uint32_t bh[4][2], bl[4][2];
            #pragma unroll
            for (int nt = 0; nt < 4; nt++) {
                const int nc = warp_n * 32 + nt * 8 + g;
                bh[nt][0] = Bh[(kc * 8 + tg) * 136 + nc];
                bh[nt][1] = Bh[(kc * 8 + tg + 4) * 136 + nc];
                bl[nt][0] = Bl[(kc * 8 + tg) * 136 + nc];
                bl[nt][1] = Bl[(kc * 8 + tg + 4) * 136 + nc];
            }
            #pragma unroll
            for (int mt = 0; mt < 4; mt++) {
                const int mr = warp_m * 64 + mt * 16;
                uint32_t ah[4], al_[4];
                ah[0]  = Ah[(kc * 8 + tg) * 136 + mr + g];
                ah[1]  = Ah[(kc * 8 + tg) * 136 + mr + g + 8];
                ah[2]  = Ah[(kc * 8 + tg + 4) * 136 + mr + g];
                ah[3]  = Ah[(kc * 8 + tg + 4) * 136 + mr + g + 8];
                al_[0] = Al[(kc * 8 + tg) * 136 + mr + g];
                al_[1] = Al[(kc * 8 + tg) * 136 + mr + g + 8];
                al_[2] = Al[(kc * 8 + tg + 4) * 136 + mr + g];
                al_[3] = Al[(kc * 8 + tg + 4) * 136 + mr + g + 8];
                #pragma unroll
                for (int nt = 0; nt < 4; nt++) {
                    mma_bf16(acc[mt][nt], al_, bh[nt]);
                    mma_bf16(acc[mt][nt], ah,  bl[nt]);
                    mma_bf16(acc[mt][nt], ah,  bh[nt]);
                }
            }
        }
    }

    // epilogue (mode 1: RoPE + K/V scatter; mode 0: +bias)
    #pragma unroll
    for (int mt = 0; mt < 4; mt++) {
        const int m = m0 + warp_m * 64 + mt * 16 + g;
        #pragma unroll
        for (int nt = 0; nt < 4; nt++) {
            const int n = n0 + warp_n * 32 + nt * 8 + 2 * tg;
            float a0 = acc[mt][nt][0], a1 = acc[mt][nt][1];
            float a2 = acc[mt][nt][2], a3 = acc[mt][nt][3];
            if (mode == 0) {
                const float b0 = bvec[n], b1 = bvec[n + 1];
                *(float2*)&C[(size_t)m * Ndim + n]       = make_float2(a0 + b0, a1 + b1);
                *(float2*)&C[(size_t)(m + 8) * Ndim + n] = make_float2(a2 + b0, a3 + b1);
            } else {
                const int seq = m & (SEQ - 1);
                const int bb  = m >> 11;
                if (n < 2 * EMB) {
                    const int d0 = n & (HD - 1);
                    const float* f0p = &freqs[(size_t)seq * HD + d0];
                    const float* f1p = f0p + (size_t)8 * HD;
                    float f0 = f0p[0], f1 = f0p[1];
                    float e0 = a0 * f0 - a1 * f1;
                    float e1 = a1 * f0 + a0 * f1;
                    float h0 = f1p[0], h1 = f1p[1];
                    float e2 = a2 * h0 - a3 * h1;
                    float e3 = a3 * h0 + a2 * h1;
                    if (n < EMB) {
                        *(float2*)&C[(size_t)m * EMB + n]       = make_float2(e0, e1);
                        *(float2*)&C[(size_t)(m + 8) * EMB + n] = make_float2(e2, e3);
                    } else {
                        const int hh = (n - EMB) >> 6;
                        const int d  = n & 63;
                        const int kt = seq >> 6, key = seq & 63;
                        uint32_t* dst = g_kvsp + ((size_t)(bb * HEADS + hh) * NKT + kt) * 8192;
                        uint32_t hp, lp;
                        split2(e0, e1, hp, lp);
                        *(uint2*)&dst[((d >> 1) * 64 + key) * 2] = make_uint2(hp, lp);
                        split2(e2, e3, hp, lp);
                        *(uint2*)&dst[((d >> 1) * 64 + key + 8) * 2] = make_uint2(hp, lp);
                    }
                } else {
                    const int hh = (n - 2 * EMB) >> 6;
                    const int d  = n & 63;
                    const int kt = seq >> 6, key = seq & 63;
                    uint32_t* dst = g_kvsp + ((size_t)(bb * HEADS + hh) * NKT + kt) * 8192 + 4096;
                    float p0 = __shfl_xor_sync(0xffffffffu, a0, 4);
                    float p1 = __shfl_xor_sync(0xffffffffu, a1, 4);
                    float p2 = __shfl_xor_sync(0xffffffffu, a2, 4);
                    float p3 = __shfl_xor_sync(0xffffffffu, a3, 4);
                    const int u0 = key >> 1;
                    uint32_t hp, lp;
                    if ((g & 1) == 0) {
                        split2(a0, p0, hp, lp);
                        *(uint2*)&dst[(u0 * 64 + d) * 2] = make_uint2(hp, lp);
                        split2(a2, p2, hp, lp);
                        *(uint2*)&dst[((u0 + 4) * 64 + d) * 2] = make_uint2(hp, lp);
                    } else {
                        split2(p1, a1, hp, lp);
                        *(uint2*)&dst[(u0 * 64 + d + 1) * 2] = make_uint2(hp, lp);
                        split2(p3, a3, hp, lp);
                        *(uint2*)&dst[((u0 + 4) * 64 + d + 1) * 2] = make_uint2(hp, lp);
                    }
                }
            }
        }
    }
}

// ---------------------------------------------------------------------------
// Flash attention (r11 core) — restructured: K+V prefetched together one tile
// ahead; ONE barrier per tile. smem: stage s at s*9216 words
// (K 32x144 at +0, V 32x144 at +4608). 73728 B total, 2 blocks/SM (reg-bound).
// ---------------------------------------------------------------------------
#define STG_W 9216

__device__ __forceinline__ void copy_kv(const uint32_t* __restrict__ gsrc,
                                        uint32_t sbase_b, int tid)
{
    // K (4096 words) + V (4096 words), src pitch 128 -> smem pitch 144
    #pragma unroll
    for (int i = 0; i < 8; i++) {
        const int q = tid + i * 256;           // 0..2047 segments of 16B
        const int half = q >> 10;              // 0=K, 1=V
        const int r = (q >> 5) & 31;
        const int c = (q & 31) * 4;
        cp16(sbase_b + (uint32_t)(half * 4608 + r * 144 + c) * 4u,
             gsrc + half * 4096 + r * 128 + c);
    }
}

__global__ __launch_bounds__(256, 2) void attn_kernel(const float* __restrict__ bias)
{
    extern __shared__ uint32_t sm[];
    uint32_t smb;
    {
        uint64_t t;
        asm("cvta.to.shared.u64 %0, %1;" : "=l"(t) : "l"(sm));
        smb = (uint32_t)t;
    }

    const int tid  = threadIdx.x;
    const int lane = tid & 31;
    const int w    = tid >> 5;
    const int g    = lane >> 2;
    const int tg   = lane & 3;
    const int q0   = blockIdx.x * 128;
    const int h    = blockIdx.y;
    const int b    = blockIdx.z;

    const int rowA = q0 + w * 16 + g;
    const float scale = 0.125f;
    const uint32_t* gtiles = g_kvsp + (size_t)(b * HEADS + h) * NKT * 8192;

    uint32_t qh[4][4], ql[4][4];
    {
        const float* qA = &g_q[(size_t)(b * SEQ + rowA) * EMB + h * HD];
        const float* qB = qA + (size_t)8 * EMB;
        #pragma unroll
        for (int ks = 0; ks < 4; ks++) {
            const int d0 = ks * 16 + 2 * tg;
            float2 x0 = *(const float2*)&qA[d0];
            float2 x1 = *(const float2*)&qB[d0];
            float2 x2 = *(const float2*)&qA[d0 + 8];
            float2 x3 = *(const float2*)&qB[d0 + 8];
            split2(x0.x * scale, x0.y * scale, qh[ks][0], ql[ks][0]);
            split2(x1.x * scale, x1.y * scale, qh[ks][1], ql[ks][1]);
            split2(x2.x * scale, x2.y * scale, qh[ks][2], ql[ks][2]);
            split2(x3.x * scale, x3.y * scale, qh[ks][3], ql[ks][3]);
        }
    }

    float o[8][4];
    #pragma unroll
    for (int nb = 0; nb < 8; nb++)
        #pragma unroll
        for (int j = 0; j < 4; j++) o[nb][j] = 0.0f;
    float m0 = -1e30f, m1 = -1e30f, l0 = 0.0f, l1 = 0.0f;

    // prologue: K0+V0 -> stage 0
    copy_kv(gtiles, smb, tid);
    cp_commit();

    for (int kt = 0; kt < NKT; kt++) {
        const int cur = kt & 1;
        asm volatile("cp.async.wait_group 0;");   // tile kt fully resident
        __syncthreads();                          // visible; stage cur^1 readers done
        if (kt + 1 < NKT) {
            copy_kv(gtiles + (size_t)(kt + 1) * 8192,
                    smb + (cur ^ 1) * (STG_W * 4), tid);
            cp_commit();
        }

        const uint32_t* Ks = sm + cur * STG_W;
        const uint32_t* Vs = Ks + 4608;

        // S = Q @ K^T (3xBF16), {hi,lo} via LDS.64
        float s[8][4];
        #pragma unroll
        for (int nb = 0; nb < 8; nb++)
            #pragma unroll
            for (int j = 0; j < 4; j++) s[nb][j] = 0.0f;

        #pragma unroll
        for (int ks = 0; ks < 4; ks++) {
            #pragma unroll
            for (int nb = 0; nb < 8; nb++) {
                uint2 w0 = *(const uint2*)&Ks[(8 * ks + tg) * 144 + (8 * nb + g) * 2];
                uint2 w1 = *(const uint2*)&Ks[(8 * ks + tg + 4) * 144 + (8 * nb + g) * 2];
                uint32_t bh[2] = {w0.x, w1.x};
                uint32_t bl[2] = {w0.y, w1.y};
                mma_bf16(s[nb], ql[ks], bh);
                mma_bf16(s[nb], qh[ks], bl);
                mma_bf16(s[nb], qh[ks], bh);
            }
        }

        // bias + online softmax
        const float* bp = &bias[((size_t)h * SEQ + rowA) * SEQ + kt * 64];
        float mx0 = -1e30f, mx1 = -1e30f;
        #pragma unroll
        for (int nb = 0; nb < 8; nb++) {
            float2 b0 = __ldcs((const float2*)(bp + nb * 8 + 2 * tg));
            float2 b1 = __ldcs((const float2*)(bp + (size_t)8 * SEQ + nb * 8 + 2 * tg));
            s[nb][0] += b0.x; s[nb][1] += b0.y;
            s[nb][2] += b1.x; s[nb][3] += b1.y;
            mx0 = fmaxf(mx0, fmaxf(s[nb][0], s[nb][1]));
            mx1 = fmaxf(mx1, fmaxf(s[nb][2], s[nb][3]));
        }
        mx0 = fmaxf(mx0, __shfl_xor_sync(0xffffffffu, mx0, 1));
        mx0 = fmaxf(mx0, __shfl_xor_sync(0xffffffffu, mx0, 2));
        mx1 = fmaxf(mx1, __shfl_xor_sync(0xffffffffu, mx1, 1));
        mx1 = fmaxf(mx1, __shfl_xor_sync(0xffffffffu, mx1, 2));
        const float nm0 = fmaxf(m0, mx0), nm1 = fmaxf(m1, mx1);
        const float al0 = __expf(m0 - nm0), al1 = __expf(m1 - nm1);
        m0 = nm0; m1 = nm1;

        float ts0 = 0.0f, ts1 = 0.0f;
        #pragma unroll
        for (int nb = 0; nb < 8; nb++) {
            s[nb][0] = __expf(s[nb][0] - nm0);
            s[nb][1] = __expf(s[nb][1] - nm0);
            s[nb][2] = __expf(s[nb][2] - nm1);
            s[nb][3] = __expf(s[nb][3] - nm1);
            ts0 += s[nb][0] + s[nb][1];
            ts1 += s[nb][2] + s[nb][3];
        }
        ts0 += __shfl_xor_sync(0xffffffffu, ts0, 1);
        ts0 += __shfl_xor_sync(0xffffffffu, ts0, 2);
        ts1 += __shfl_xor_sync(0xffffffffu, ts1, 1);
        ts1 += __shfl_xor_sync(0xffffffffu, ts1, 2);
        l0 = l0 * al0 + ts0;
        l1 = l1 * al1 + ts1;
        #pragma unroll
        for (int nb = 0; nb < 8; nb++) {
            o[nb][0] *= al0; o[nb][1] *= al0;
            o[nb][2] *= al1; o[nb][3] *= al1;
        }

        // O += P @ V (V already resident in this stage)
        #pragma unroll
        for (int j = 0; j < 4; j++) {
            uint32_t ah[4], al_[4];
            split2(s[2 * j][0],     s[2 * j][1],     ah[0], al_[0]);
            split2(s[2 * j][2],     s[2 * j][3],     ah[1], al_[1]);
            split2(s[2 * j + 1][0], s[2 * j + 1][1], ah[2], al_[2]);
            split2(s[2 * j + 1][2], s[2 * j + 1][3], ah[3], al_[3]);
            #pragma unroll
            for (int nb = 0; nb < 8; nb++) {
                uint2 w0 = *(const uint2*)&Vs[(8 * j + tg) * 144 + (8 * nb + g) * 2];
                uint2 w1 = *(const uint2*)&Vs[(8 * j + tg + 4) * 144 + (8 * nb + g) * 2];
                uint32_t vh[2] = {w0.x, w1.x};
                uint32_t vl[2] = {w0.y, w1.y};
                mma_bf16(o[nb], al_, vh);
                mma_bf16(o[nb], ah,  vl);
                mma_bf16(o[nb], ah,  vh);
            }
        }
    }

    // epilogue: normalize + write pre-split proj-A operand
    const float inv0 = 1.0f / l0, inv1 = 1.0f / l1;
    const int mA = b * SEQ + rowA;
    #pragma unroll
    for (int nb = 0; nb < 8; nb++) {
        const int kp = h * 32 + nb * 4 + tg;
        uint32_t hh, ll;
        split2(o[nb][0] * inv0, o[nb][1] * inv0, hh, ll);
        g_ah[(size_t)kp * MROWS + mA] = hh;
        g_al[(size_t)kp * MROWS + mA] = ll;
        split2(o[nb][2] * inv1, o[nb][3] * inv1, hh, ll);
        g_ah[(size_t)kp * MROWS + mA + 8] = hh;
        g_al[(size_t)kp * MROWS + mA + 8] = ll;
    }
}

// ---------------------------------------------------------------------------
extern "C" void kernel_launch(void* const* d_in, const int* in_sizes, int n_in,
                              void* d_out, int out_size)
{
    const float* x      = (const float*)d_in[0];
    const float* freqs  = (const float*)d_in[1];
    const float* bias   = (const float*)d_in[2];
    const float* w_qkv  = (const float*)d_in[3];
    const float* w_proj = (const float*)d_in[4];
    const float* b_proj = (const float*)d_in[5];
    float* out = (float*)d_out;

    float* q_ptr; cudaGetSymbolAddress((void**)&q_ptr, g_q);
    uint32_t *xh, *xl, *wqh, *wql, *wph, *wpl, *ah, *al;
    cudaGetSymbolAddress((void**)&xh,  g_xh);
    cudaGetSymbolAddress((void**)&xl,  g_xl);
    cudaGetSymbolAddress((void**)&wqh, g_wqh);
    cudaGetSymbolAddress((void**)&wql, g_wql);
    cudaGetSymbolAddress((void**)&wph, g_wph);
    cudaGetSymbolAddress((void**)&wpl, g_wpl);
    cudaGetSymbolAddress((void**)&ah,  g_ah);
    cudaGetSymbolAddress((void**)&al,  g_al);

    const int gemm_smem = 2 * 8704 * 4;     // 69632 B
    const int attn_smem = 2 * STG_W * 4;    // 73728 B
    cudaFuncSetAttribute(gemm_sp, cudaFuncAttributeMaxDynamicSharedMemorySize, gemm_smem);
    cudaFuncSetAttribute(attn_kernel, cudaFuncAttributeMaxDynamicSharedMemorySize, attn_smem);

    // attn is our 4th launch -> ncu capture slot
    prep_a<<<dim3(EMB / 32, MROWS / 64), 256>>>(x, xh, xl);                          // 1
    prep_w<<<dim3(QKVN / 512, EMB / 2), 128>>>(w_qkv, wqh, wql, QKVN);               // 2
    gemm_sp<<<dim3(QKVN / 128, MROWS / 128), 256, gemm_smem>>>(                      // 3
        xh, xl, wqh, wql, q_ptr, QKVN, freqs, nullptr, 1);
    attn_kernel<<<dim3(SEQ / 128, HEADS, BATCH), 256, attn_smem>>>(bias);            // 4 <- profiled
    prep_w<<<dim3(EMB / 512, EMB / 2), 128>>>(w_proj, wph, wpl, EMB);                // 5
    gemm_sp<<<dim3(EMB / 128, MROWS / 128), 256, gemm_smem>>>(                       // 6
        ah, al, wph, wpl, out, EMB, nullptr, b_proj, 0);
}

// round 16
// speedup vs baseline: 1.1596x; 1.0231x over previous
#include <cuda_runtime.h>
#include <cuda_bf16.h>
#include <cstdint>

#define BATCH 2
#define SEQ   2048
#define HEADS 16
#define HD    64
#define EMB   1024
#define MROWS (BATCH*SEQ)
#define QKVN  (3*EMB)
#define NKT   (SEQ/64)           // 32 key tiles

// roped q, fp32 dense [MROWS][EMB]
__device__ float g_q[(size_t)MROWS * EMB];                               // 16.8 MB
// K/V tiles, LDS.128-fragment layout:
//   per (b,h,kt) tile 8192 words.
//   K at 0:    word(key,dp) = key*64 + (dp>>3)*16 + (dp&3)*4 + ((dp>>2)&1)*2
//              (+0 hi, +1 lo);  dp = d/2, word = {K[key][2dp],K[key][2dp+1]}
//   V at 4096: word(d,kp)  = d*64  + (kp>>3)*16 + (kp&3)*4 + ((kp>>2)&1)*2
//              (+0 hi, +1 lo);  kp = key/2, word = {V[2kp][d],V[2kp+1][d]}
__device__ uint32_t g_kvsp[(size_t)BATCH * HEADS * NKT * 8192];          // 67.1 MB
// Pre-split GEMM operands (separate hi/lo): [kp][M or N]
__device__ uint32_t g_xh[(size_t)(EMB/2) * MROWS],  g_xl[(size_t)(EMB/2) * MROWS];
__device__ uint32_t g_wqh[(size_t)(EMB/2) * QKVN],  g_wql[(size_t)(EMB/2) * QKVN];
__device__ uint32_t g_wph[(size_t)(EMB/2) * EMB],   g_wpl[(size_t)(EMB/2) * EMB];
__device__ uint32_t g_ah[(size_t)(EMB/2) * MROWS],  g_al[(size_t)(EMB/2) * MROWS];

__device__ __forceinline__ uint32_t pack_bf16x2(float e0, float e1) {
    uint32_t r;
    asm("cvt.rn.bf16x2.f32 %0, %1, %2;" : "=r"(r) : "f"(e1), "f"(e0));
    return r;
}
__device__ __forceinline__ void split2(float x, float y, uint32_t& hp, uint32_t& lp) {
    float hx = __bfloat162float(__float2bfloat16_rn(x));
    float hy = __bfloat162float(__float2bfloat16_rn(y));
    hp = pack_bf16x2(hx, hy);
    lp = pack_bf16x2(x - hx, y - hy);
}
__device__ __forceinline__ void mma_bf16(float c[4], const uint32_t a[4], const uint32_t b[2]) {
    asm volatile(
        "mma.sync.aligned.m16n8k16.row.col.f32.bf16.bf16.f32 "
        "{%0,%1,%2,%3}, {%4,%5,%6,%7}, {%8,%9}, {%0,%1,%2,%3};"
        : "+f"(c[0]), "+f"(c[1]), "+f"(c[2]), "+f"(c[3])
        : "r"(a[0]), "r"(a[1]), "r"(a[2]), "r"(a[3]), "r"(b[0]), "r"(b[1]));
}
__device__ __forceinline__ void cp16(uint32_t dst, const void* src) {
    asm volatile("cp.async.cg.shared.global [%0], [%1], 16;" :: "r"(dst), "l"(src));
}
__device__ __forceinline__ void cp_commit() {
    asm volatile("cp.async.commit_group;");
}
// K/V tile word index helpers (layout above)
__device__ __forceinline__ uint32_t wordK(int key, int dp) {
    return (uint32_t)(key * 64 + ((dp >> 3) << 4) + ((dp & 3) << 2) + (((dp >> 2) & 1) << 1));
}
__device__ __forceinline__ uint32_t wordV(int d, int kp) {
    return (uint32_t)(d * 64 + ((kp >> 3) << 4) + ((kp & 3) << 2) + (((kp >> 2) & 1) << 1));
}

// ---------------------------------------------------------------------------
// prep_a: split fp32 A[M][K] into Ah/Al[kp][M] via smem transpose (r11)
// ---------------------------------------------------------------------------
__global__ __launch_bounds__(256) void prep_a(const float* __restrict__ A,
                                              uint32_t* __restrict__ dh,
                                              uint32_t* __restrict__ dl)
{
    __shared__ float stage[64 * 33];
    const int tid = threadIdx.x;
    const int k0 = blockIdx.x * 32;
    const int m0 = blockIdx.y * 64;

    #pragma unroll
    for (int j = 0; j < 2; j++) {
        const int f = tid + j * 256;
        const int r = f >> 3;
        const int c4 = (f & 7) * 4;
        float4 v = *(const float4*)&A[(size_t)(m0 + r) * EMB + k0 + c4];
        stage[r * 33 + c4 + 0] = v.x;
        stage[r * 33 + c4 + 1] = v.y;
        stage[r * 33 + c4 + 2] = v.z;
        stage[r * 33 + c4 + 3] = v.w;
    }
    __syncthreads();

    const int m_l = tid & 63;
    #pragma unroll
    for (int j = 0; j < 4; j++) {
        const int kp_l = (tid >> 6) + j * 4;
        float a = stage[m_l * 33 + 2 * kp_l];
        float b = stage[m_l * 33 + 2 * kp_l + 1];
        uint32_t h, l;
        split2(a, b, h, l);
        dh[(size_t)(k0 / 2 + kp_l) * MROWS + m0 + m_l] = h;
        dl[(size_t)(k0 / 2 + kp_l) * MROWS + m0 + m_l] = l;
    }
}

// ---------------------------------------------------------------------------
// prep_w: split fp32 W[K][N] into Wh/Wl[kp][N] (r11)
// ---------------------------------------------------------------------------
__global__ __launch_bounds__(128) void prep_w(const float* __restrict__ W,
                                              uint32_t* __restrict__ dh,
                                              uint32_t* __restrict__ dl, int N)
{
    const int n  = blockIdx.x * 512 + threadIdx.x * 4;
    const int kp = blockIdx.y;
    float4 r0 = *(const float4*)&W[(size_t)(2 * kp) * N + n];
    float4 r1 = *(const float4*)&W[(size_t)(2 * kp + 1) * N + n];
    uint32_t h[4], l[4];
    split2(r0.x, r1.x, h[0], l[0]);
    split2(r0.y, r1.y, h[1], l[1]);
    split2(r0.z, r1.z, h[2], l[2]);
    split2(r0.w, r1.w, h[3], l[3]);
    *(uint4*)&dh[(size_t)kp * N + n] = make_uint4(h[0], h[1], h[2], h[3]);
    *(uint4*)&dl[(size_t)kp * N + n] = make_uint4(l[0], l[1], l[2], l[3]);
}

// ---------------------------------------------------------------------------
// 3xBF16 GEMM (r15 core, single barrier per k-iter).
// mode 1 epilogue scatters K/V into the LDS.128-fragment tile layout.
// ---------------------------------------------------------------------------
__global__ __launch_bounds__(256, 2) void gemm_sp(
    const uint32_t* __restrict__ AhG, const uint32_t* __restrict__ AlG,
    const uint32_t* __restrict__ BhG, const uint32_t* __restrict__ BlG,
    float* __restrict__ C, int Ndim,
    const float* __restrict__ freqs,
    const float* __restrict__ bvec, int mode)
{
    extern __shared__ uint32_t sm[];
    uint32_t smb;
    {
        uint64_t t;
        asm("cvta.to.shared.u64 %0, %1;" : "=l"(t) : "l"(sm));
        smb = (uint32_t)t;
    }

    const int tid  = threadIdx.x;
    const int lane = tid & 31;
    const int warp = tid >> 5;
    const int g    = lane >> 2;
    const int tg   = lane & 3;
    const int warp_m = warp >> 2;
    const int warp_n = warp & 3;
    const int m0 = blockIdx.y * 128;
    const int n0 = blockIdx.x * 128;

    float acc[4][4][4];
    #pragma unroll
    for (int mt = 0; mt < 4; mt++)
        #pragma unroll
        for (int nt = 0; nt < 4; nt++)
            #pragma unroll
            for (int c = 0; c < 4; c++) acc[mt][nt][c] = 0.0f;

    const uint32_t* gArr[4] = {AhG, AlG, BhG, BlG};

    // prologue: tile 0 -> stage 0
    {
        #pragma unroll
        for (int i = 0; i < 8; i++) {
            const int f = tid + i * 256;
            const int arr = f >> 9, r = (f >> 5) & 15, seg = f & 31;
            const uint32_t* src = (arr < 2)
                ? gArr[arr] + (size_t)r * MROWS + m0 + seg * 4
                : gArr[arr] + (size_t)r * Ndim + n0 + seg * 4;
            cp16(smb + (uint32_t)(arr * 2176 + r * 136 + seg * 4) * 4u, src);
        }
        cp_commit();
    }

    const int NIT = EMB / 32;
    for (int it = 0; it < NIT; it++) {
        const int cur = it & 1;
        asm volatile("cp.async.wait_group 0;");
        __syncthreads();
        if (it + 1 < NIT) {
            const int kp0 = (it + 1) * 16;
            const uint32_t sb = smb + (uint32_t)((cur ^ 1) * 8704) * 4u;
            #pragma unroll
            for (int i = 0; i < 8; i++) {
                const int f = tid + i * 256;
                const int arr = f >> 9, r = (f >> 5) & 15, seg = f & 31;
                const uint32_t* src = (arr < 2)
                    ? gArr[arr] + (size_t)(kp0 + r) * MROWS + m0 + seg * 4
                    : gArr[arr] + (size_t)(kp0 + r) * Ndim + n0 + seg * 4;
                cp16(sb + (uint32_t)(arr * 2176 + r * 136 + seg * 4) * 4u, src);
            }
            cp_commit();
        }

        const uint32_t* Ah = sm + cur * 8704;
        const uint32_t* Al = Ah + 2176;
        const uint32_t* Bh = Ah + 4352;
        const uint32_t* Bl = Ah + 6528;

        #pragma unroll
        for (int kc = 0; kc < 2; kc++) {
            uint32_t bh[4][2], bl[4][2];
            #pragma unroll
            for (int nt = 0; nt < 4; nt++) {
                const int nc = warp_n * 32 + nt * 8 + g;
                bh[nt][0] = Bh[(kc * 8 + tg) * 136 + nc];
                bh[nt][1] = Bh[(kc * 8 + tg + 4) * 136 + nc];
                bl[nt][0] = Bl[(kc * 8 + tg) * 136 + nc];
                bl[nt][1] = Bl[(kc * 8 + tg + 4) * 136 + nc];
            }
            #pragma unroll
            for (int mt = 0; mt < 4; mt++) {
                const int mr = warp_m * 64 + mt * 16;
                uint32_t ah[4], al_[4];
                ah[0]  = Ah[(kc * 8 + tg) * 136 + mr + g];
                ah[1]  = Ah[(kc * 8 + tg) * 136 + mr + g + 8];
                ah[2]  = Ah[(kc * 8 + tg + 4) * 136 + mr + g];
                ah[3]  = Ah[(kc * 8 + tg + 4) * 136 + mr + g + 8];
                al_[0] = Al[(kc * 8 + tg) * 136 + mr + g];
                al_[1] = Al[(kc * 8 + tg) * 136 + mr + g + 8];
                al_[2] = Al[(kc * 8 + tg + 4) * 136 + mr + g];
                al_[3] = Al[(kc * 8 + tg + 4) * 136 + mr + g + 8];
                #pragma unroll
                for (int nt = 0; nt < 4; nt++) {
                    mma_bf16(acc[mt][nt], al_, bh[nt]);
                    mma_bf16(acc[mt][nt], ah,  bl[nt]);
                    mma_bf16(acc[mt][nt], ah,  bh[nt]);
                }
            }
        }
    }

    // epilogue (mode 1: RoPE + K/V scatter into fragment layout; mode 0: +bias)
    #pragma unroll
    for (int mt = 0; mt < 4; mt++) {
        const int m = m0 + warp_m * 64 + mt * 16 + g;
        #pragma unroll
        for (int nt = 0; nt < 4; nt++) {
            const int n = n0 + warp_n * 32 + nt * 8 + 2 * tg;
            float a0 = acc[mt][nt][0], a1 = acc[mt][nt][1];
            float a2 = acc[mt][nt][2], a3 = acc[mt][nt][3];
            if (mode == 0) {
                const float b0 = bvec[n], b1 = bvec[n + 1];
                *(float2*)&C[(size_t)m * Ndim + n]       = make_float2(a0 + b0, a1 + b1);
                *(float2*)&C[(size_t)(m + 8) * Ndim + n] = make_float2(a2 + b0, a3 + b1);
            } else {
                const int seq = m & (SEQ - 1);
                const int bb  = m >> 11;
                if (n < 2 * EMB) {
                    const int d0 = n & (HD - 1);
                    const float* f0p = &freqs[(size_t)seq * HD + d0];
                    const float* f1p = f0p + (size_t)8 * HD;
                    float f0 = f0p[0], f1 = f0p[1];
                    float e0 = a0 * f0 - a1 * f1;
                    float e1 = a1 * f0 + a0 * f1;
                    float h0 = f1p[0], h1 = f1p[1];
                    float e2 = a2 * h0 - a3 * h1;
                    float e3 = a3 * h0 + a2 * h1;
                    if (n < EMB) {
                        *(float2*)&C[(size_t)m * EMB + n]       = make_float2(e0, e1);
                        *(float2*)&C[(size_t)(m + 8) * EMB + n] = make_float2(e2, e3);
                    } else {
                        // K scatter: dp = d/2
                        const int hh = (n - EMB) >> 6;
                        const int d  = n & 63;
                        const int dp = d >> 1;
                        const int kt = seq >> 6, key = seq & 63;
                        uint32_t* dst = g_kvsp + ((size_t)(bb * HEADS + hh) * NKT + kt) * 8192;
                        uint32_t hp, lp;
                        split2(e0, e1, hp, lp);
                        *(uint2*)&dst[wordK(key, dp)]     = make_uint2(hp, lp);
                        split2(e2, e3, hp, lp);
                        *(uint2*)&dst[wordK(key + 8, dp)] = make_uint2(hp, lp);
                    }
                } else {
                    // V scatter (adjacent-key pairing via shfl)
                    const int hh = (n - 2 * EMB) >> 6;
                    const int d  = n & 63;
                    const int kt = seq >> 6, key = seq & 63;
                    uint32_t* dst = g_kvsp + ((size_t)(bb * HEADS + hh) * NKT + kt) * 8192 + 4096;
                    float p0 = __shfl_xor_sync(0xffffffffu, a0, 4);
                    float p1 = __shfl_xor_sync(0xffffffffu, a1, 4);
                    float p2 = __shfl_xor_sync(0xffffffffu, a2, 4);
                    float p3 = __shfl_xor_sync(0xffffffffu, a3, 4);
                    const int u0 = key >> 1;
                    uint32_t hp, lp;
                    if ((g & 1) == 0) {
                        split2(a0, p0, hp, lp);
                        *(uint2*)&dst[wordV(d, u0)]     = make_uint2(hp, lp);
                        split2(a2, p2, hp, lp);
                        *(uint2*)&dst[wordV(d, u0 + 4)] = make_uint2(hp, lp);
                    } else {
                        split2(p1, a1, hp, lp);
                        *(uint2*)&dst[wordV(d + 1, u0)]     = make_uint2(hp, lp);
                        split2(p3, a3, hp, lp);
                        *(uint2*)&dst[wordV(d + 1, u0 + 4)] = make_uint2(hp, lp);
                    }
                }
            }
        }
    }
}

// ---------------------------------------------------------------------------
// Flash attention (r15 structure): 8 warps x 16 q-rows, single barrier/tile,
// K+V prefetched one tile ahead. Fragment loads are now single LDS.128:
// smem row pitch 80 words -> octet phases hit banks {0,4,...,28}.
// smem: stage s at s*10240 words (K rows 64x80 at +0, V rows 64x80 at +5120).
// 81920 B total, 2 blocks/SM.
// ---------------------------------------------------------------------------
#define STG_W 10240

__device__ __forceinline__ void copy_kv(const uint32_t* __restrict__ gsrc,
                                        uint32_t sbase_b, int tid)
{
    // K (4096 w) + V (4096 w): 64-word rows -> 80-word-pitch smem rows
    #pragma unroll
    for (int i = 0; i < 8; i++) {
        const int q = tid + i * 256;           // 0..2047 segments of 16B
        const int half = q >> 10;              // 0=K, 1=V
        const int r = (q >> 4) & 63;           // row 0..63
        const int c = (q & 15) * 4;            // 16 segs per row
        cp16(sbase_b + (uint32_t)(half * 5120 + r * 80 + c) * 4u,
             gsrc + half * 4096 + r * 64 + c);
    }
}

__global__ __launch_bounds__(256, 2) void attn_kernel(const float* __restrict__ bias)
{
    extern __shared__ uint32_t sm[];
    uint32_t smb;
    {
        uint64_t t;
        asm("cvta.to.shared.u64 %0, %1;" : "=l"(t) : "l"(sm));
        smb = (uint32_t)t;
    }

    const int tid  = threadIdx.x;
    const int lane = tid & 31;
    const int w    = tid >> 5;
    const int g    = lane >> 2;
    const int tg   = lane & 3;
    const int q0   = blockIdx.x * 128;
    const int h    = blockIdx.y;
    const int b    = blockIdx.z;

    const int rowA = q0 + w * 16 + g;
    const float scale = 0.125f;
    const uint32_t* gtiles = g_kvsp + (size_t)(b * HEADS + h) * NKT * 8192;

    uint32_t qh[4][4], ql[4][4];
    {
        const float* qA = &g_q[(size_t)(b * SEQ + rowA) * EMB + h * HD];
        const float* qB = qA + (size_t)8 * EMB;
        #pragma unroll
        for (int ks = 0; ks < 4; ks++) {
            const int d0 = ks * 16 + 2 * tg;
            float2 x0 = *(const float2*)&qA[d0];
            float2 x1 = *(const float2*)&qB[d0];
            float2 x2 = *(const float2*)&qA[d0 + 8];
            float2 x3 = *(const float2*)&qB[d0 + 8];
            split2(x0.x * scale, x0.y * scale, qh[ks][0], ql[ks][0]);
            split2(x1.x * scale, x1.y * scale, qh[ks][1], ql[ks][1]);
            split2(x2.x * scale, x2.y * scale, qh[ks][2], ql[ks][2]);
            split2(x3.x * scale, x3.y * scale, qh[ks][3], ql[ks][3]);
        }
    }

    float o[8][4];
    #pragma unroll
    for (int nb = 0; nb < 8; nb++)
        #pragma unroll
        for (int j = 0; j < 4; j++) o[nb][j] = 0.0f;
    float m0 = -1e30f, m1 = -1e30f, l0 = 0.0f, l1 = 0.0f;

    // prologue: K0+V0 -> stage 0
    copy_kv(gtiles, smb, tid);
    cp_commit();

    for (int kt = 0; kt < NKT; kt++) {
        const int cur = kt & 1;
        asm volatile("cp.async.wait_group 0;");
        __syncthreads();
        if (kt + 1 < NKT) {
            copy_kv(gtiles + (size_t)(kt + 1) * 8192,
                    smb + (cur ^ 1) * (STG_W * 4), tid);
            cp_commit();
        }

        const uint32_t* Ks = sm + cur * STG_W;
        const uint32_t* Vs = Ks + 5120;

        // S = Q @ K^T (3xBF16), one LDS.128 per B-fragment pair
        float s[8][4];
        #pragma unroll
        for (int nb = 0; nb < 8; nb++)
            #pragma unroll
            for (int j = 0; j < 4; j++) s[nb][j] = 0.0f;

        #pragma unroll
        for (int ks = 0; ks < 4; ks++) {
            #pragma unroll
            for (int nb = 0; nb < 8; nb++) {
                uint4 f = *(const uint4*)&Ks[(8 * nb + g) * 80 + ks * 16 + tg * 4];
                uint32_t bh[2] = {f.x, f.z};
                uint32_t bl[2] = {f.y, f.w};
                mma_bf16(s[nb], ql[ks], bh);
                mma_bf16(s[nb], qh[ks], bl);
                mma_bf16(s[nb], qh[ks], bh);
            }
        }

        // bias + online softmax
        const float* bp = &bias[((size_t)h * SEQ + rowA) * SEQ + kt * 64];
        float mx0 = -1e30f, mx1 = -1e30f;
        #pragma unroll
        for (int nb = 0; nb < 8; nb++) {
            float2 b0 = __ldcs((const float2*)(bp + nb * 8 + 2 * tg));
            float2 b1 = __ldcs((const float2*)(bp + (size_t)8 * SEQ + nb * 8 + 2 * tg));
            s[nb][0] += b0.x; s[nb][1] += b0.y;
            s[nb][2] += b1.x; s[nb][3] += b1.y;
            mx0 = fmaxf(mx0, fmaxf(s[nb][0], s[nb][1]));
            mx1 = fmaxf(mx1, fmaxf(s[nb][2], s[nb][3]));
        }
        mx0 = fmaxf(mx0, __shfl_xor_sync(0xffffffffu, mx0, 1));
        mx0 = fmaxf(mx0, __shfl_xor_sync(0xffffffffu, mx0, 2));
        mx1 = fmaxf(mx1, __shfl_xor_sync(0xffffffffu, mx1, 1));
        mx1 = fmaxf(mx1, __shfl_xor_sync(0xffffffffu, mx1, 2));
        const float nm0 = fmaxf(m0, mx0), nm1 = fmaxf(m1, mx1);
        const float al0 = __expf(m0 - nm0), al1 = __expf(m1 - nm1);
        m0 = nm0; m1 = nm1;

        float ts0 = 0.0f, ts1 = 0.0f;
        #pragma unroll
        for (int nb = 0; nb < 8; nb++) {
            s[nb][0] = __expf(s[nb][0] - nm0);
            s[nb][1] = __expf(s[nb][1] - nm0);
            s[nb][2] = __expf(s[nb][2] - nm1);
            s[nb][3] = __expf(s[nb][3] - nm1);
            ts0 += s[nb][0] + s[nb][1];
            ts1 += s[nb][2] + s[nb][3];
        }
        ts0 += __shfl_xor_sync(0xffffffffu, ts0, 1);
        ts0 += __shfl_xor_sync(0xffffffffu, ts0, 2);
        ts1 += __shfl_xor_sync(0xffffffffu, ts1, 1);
        ts1 += __shfl_xor_sync(0xffffffffu, ts1, 2);
        l0 = l0 * al0 + ts0;
        l1 = l1 * al1 + ts1;
        #pragma unroll
        for (int nb = 0; nb < 8; nb++) {
            o[nb][0] *= al0; o[nb][1] *= al0;
            o[nb][2] *= al1; o[nb][3] *= al1;
        }

        // O += P @ V (3xBF16), one LDS.128 per V-fragment pair
        #pragma unroll
        for (int j = 0; j < 4; j++) {
            uint32_t ah[4], al_[4];
            split2(s[2 * j][0],     s[2 * j][1],     ah[0], al_[0]);
            split2(s[2 * j][2],     s[2 * j][3],     ah[1], al_[1]);
            split2(s[2 * j + 1][0], s[2 * j + 1][1], ah[2], al_[2]);
            split2(s[2 * j + 1][2], s[2 * j + 1][3], ah[3], al_[3]);
            #pragma unroll
            for (int nb = 0; nb < 8; nb++) {
                uint4 f = *(const uint4*)&Vs[(8 * nb + g) * 80 + j * 16 + tg * 4];
                uint32_t vh[2] = {f.x, f.z};
                uint32_t vl[2] = {f.y, f.w};
                mma_bf16(o[nb], al_, vh);
                mma_bf16(o[nb], ah,  vl);
                mma_bf16(o[nb], ah,  vh);
            }
        }
    }

    // epilogue: normalize + write pre-split proj-A operand
    const float inv0 = 1.0f / l0, inv1 = 1.0f / l1;
    const int mA = b * SEQ + rowA;
    #pragma unroll
    for (int nb = 0; nb < 8; nb++) {
        const int kp = h * 32 + nb * 4 + tg;
        uint32_t hh, ll;
        split2(o[nb][0] * inv0, o[nb][1] * inv0, hh, ll);
        g_ah[(size_t)kp * MROWS + mA] = hh;
        g_al[(size_t)kp * MROWS + mA] = ll;
        split2(o[nb][2] * inv1, o[nb][3] * inv1, hh, ll);
        g_ah[(size_t)kp * MROWS + mA + 8] = hh;
        g_al[(size_t)kp * MROWS + mA + 8] = ll;
    }
}

// ---------------------------------------------------------------------------
extern "C" void kernel_launch(void* const* d_in, const int* in_sizes, int n_in,
                              void* d_out, int out_size)
{
    const float* x      = (const float*)d_in[0];
    const float* freqs  = (const float*)d_in[1];
    const float* bias   = (const float*)d_in[2];
    const float* w_qkv  = (const float*)d_in[3];
    const float* w_proj = (const float*)d_in[4];
    const float* b_proj = (const float*)d_in[5];
    float* out = (float*)d_out;

    float* q_ptr; cudaGetSymbolAddress((void**)&q_ptr, g_q);
    uint32_t *xh, *xl, *wqh, *wql, *wph, *wpl, *ah, *al;
    cudaGetSymbolAddress((void**)&xh,  g_xh);
    cudaGetSymbolAddress((void**)&xl,  g_xl);
    cudaGetSymbolAddress((void**)&wqh, g_wqh);
    cudaGetSymbolAddress((void**)&wql, g_wql);
    cudaGetSymbolAddress((void**)&wph, g_wph);
    cudaGetSymbolAddress((void**)&wpl, g_wpl);
    cudaGetSymbolAddress((void**)&ah,  g_ah);
    cudaGetSymbolAddress((void**)&al,  g_al);

    const int gemm_smem = 2 * 8704 * 4;     // 69632 B
    const int attn_smem = 2 * STG_W * 4;    // 81920 B
    cudaFuncSetAttribute(gemm_sp, cudaFuncAttributeMaxDynamicSharedMemorySize, gemm_smem);
    cudaFuncSetAttribute(attn_kernel, cudaFuncAttributeMaxDynamicSharedMemorySize, attn_smem);

    // attn is our 4th launch -> ncu capture slot
    prep_a<<<dim3(EMB / 32, MROWS / 64), 256>>>(x, xh, xl);                          // 1
    prep_w<<<dim3(QKVN / 512, EMB / 2), 128>>>(w_qkv, wqh, wql, QKVN);               // 2
    gemm_sp<<<dim3(QKVN / 128, MROWS / 128), 256, gemm_smem>>>(                      // 3
        xh, xl, wqh, wql, q_ptr, QKVN, freqs, nullptr, 1);
    attn_kernel<<<dim3(SEQ / 128, HEADS, BATCH), 256, attn_smem>>>(bias);            // 4 <- profiled
    prep_w<<<dim3(EMB / 512, EMB / 2), 128>>>(w_proj, wph, wpl, EMB);                // 5
    gemm_sp<<<dim3(EMB / 128, MROWS / 128), 256, gemm_smem>>>(                       // 6
        ah, al, wph, wpl, out, EMB, nullptr, b_proj, 0);
}